// round 1
// baseline (speedup 1.0000x reference)
#include <cuda_runtime.h>
#include <math.h>

#define B_ 2
#define T_ 2048
#define C_ 1024
#define H_ 16
#define D_ 64
#define M_ (B_*T_)   // 4096

// Scratch (device globals -- allocation-free)
__device__ float g_Q[B_*H_*T_*D_];
__device__ float g_K[B_*H_*T_*D_];
__device__ float g_V[B_*H_*T_*D_];
__device__ float g_Y[B_*T_*C_];

// ---------------------------------------------------------------------------
// Projection GEMM: C[m,n] = sum_k X[m,k] * W[n,k]   (torch Linear: y = x W^T)
// M=4096, N=1024, K=1024.  64x64 block tile, BK=16, 256 threads, 4x4 micro.
// MODE 0: scatter output to [B,H,T,D] layout (for Q/K/V)
// MODE 1: plain [M,N] output (for final projection)
// ---------------------------------------------------------------------------
template<int MODE>
__global__ void __launch_bounds__(256) proj_kernel(
    const float* __restrict__ X, const float* __restrict__ W,
    float* __restrict__ out)
{
    __shared__ float Xs[16][68];   // [k][m], padded
    __shared__ float Ws[16][68];   // [k][n], padded
    const int bm = blockIdx.y * 64;
    const int bn = blockIdx.x * 64;
    const int tid = threadIdx.x;
    const int ty = tid >> 4, tx = tid & 15;
    const int lrow = tid >> 2;          // 0..63
    const int lk   = (tid & 3) * 4;     // 0,4,8,12

    float acc[4][4] = {};

    const float* xp = X + (bm + lrow) * C_ + lk;
    const float* wp = W + (bn + lrow) * C_ + lk;

    for (int k0 = 0; k0 < C_; k0 += 16) {
        float4 xv = *(const float4*)(xp + k0);
        float4 wv = *(const float4*)(wp + k0);
        Xs[lk+0][lrow] = xv.x; Xs[lk+1][lrow] = xv.y;
        Xs[lk+2][lrow] = xv.z; Xs[lk+3][lrow] = xv.w;
        Ws[lk+0][lrow] = wv.x; Ws[lk+1][lrow] = wv.y;
        Ws[lk+2][lrow] = wv.z; Ws[lk+3][lrow] = wv.w;
        __syncthreads();
        #pragma unroll
        for (int k = 0; k < 16; k++) {
            float4 a4 = *(const float4*)&Xs[k][ty*4];
            float4 b4 = *(const float4*)&Ws[k][tx*4];
            float av[4] = {a4.x, a4.y, a4.z, a4.w};
            float bv[4] = {b4.x, b4.y, b4.z, b4.w};
            #pragma unroll
            for (int i = 0; i < 4; i++)
                #pragma unroll
                for (int j = 0; j < 4; j++)
                    acc[i][j] += av[i] * bv[j];
        }
        __syncthreads();
    }

    #pragma unroll
    for (int i = 0; i < 4; i++) {
        const int m = bm + ty*4 + i;
        #pragma unroll
        for (int j = 0; j < 4; j++) {
            const int n = bn + tx*4 + j;
            if (MODE == 0) {
                const int b = m >> 11;           // m / T_
                const int t = m & (T_ - 1);
                const int h = n >> 6;            // n / D_
                const int d = n & 63;
                out[(((b*H_ + h)*T_ + t) << 6) + d] = acc[i][j];
            } else {
                out[m * C_ + n] = acc[i][j];
            }
        }
    }
}

// ---------------------------------------------------------------------------
// Flash attention, causal. One block per (q-tile of 64, b*h).
// 256 threads, 4x4 micro-tiles over the 64x64 S / O tiles.
// Row reductions via shfl-xor within the 16-lane tx groups.
// ---------------------------------------------------------------------------
__global__ void __launch_bounds__(256) attn_kernel()
{
    extern __shared__ float sm[];
    float* Qs  = sm;                 // [64][65]  Q[q][d]
    float* KPs = sm + 64*65;         // [64][65]  K[kv][d], later P[q][kv]
    float* Vs  = sm + 2*64*65;       // [64][65]  V[kv][d]

    const int bh = blockIdx.y;
    const int qt = gridDim.x - 1 - blockIdx.x;   // heavy tiles scheduled first
    const int b  = bh >> 4;          // / H_
    const int h  = bh & 15;
    const float* Qg = g_Q + (size_t)bh * (T_*D_);
    const float* Kg = g_K + (size_t)bh * (T_*D_);
    const float* Vg = g_V + (size_t)bh * (T_*D_);
    const int q0 = qt * 64;
    const int tid = threadIdx.x;
    const int ty = tid >> 4, tx = tid & 15;

    // Load Q tile
    {
        const int r = tid >> 4;           // 0..15
        const int c = (tid & 15) * 4;     // 0..60
        #pragma unroll
        for (int it = 0; it < 4; it++) {
            const int row = r + it*16;
            float4 v = *(const float4*)(Qg + (q0 + row)*D_ + c);
            Qs[row*65 + c + 0] = v.x;
            Qs[row*65 + c + 1] = v.y;
            Qs[row*65 + c + 2] = v.z;
            Qs[row*65 + c + 3] = v.w;
        }
    }

    float acc[4][4] = {};
    float mi[4], li[4];
    #pragma unroll
    for (int i = 0; i < 4; i++) { mi[i] = -1e30f; li[i] = 0.0f; }

    for (int kt = 0; kt <= qt; kt++) {
        __syncthreads();   // previous PV readers done before overwrite
        {
            const int r = tid >> 4;
            const int c = (tid & 15) * 4;
            #pragma unroll
            for (int it = 0; it < 4; it++) {
                const int row = r + it*16;
                float4 kv = *(const float4*)(Kg + (kt*64 + row)*D_ + c);
                KPs[row*65 + c + 0] = kv.x;
                KPs[row*65 + c + 1] = kv.y;
                KPs[row*65 + c + 2] = kv.z;
                KPs[row*65 + c + 3] = kv.w;
                float4 vv = *(const float4*)(Vg + (kt*64 + row)*D_ + c);
                Vs[row*65 + c + 0] = vv.x;
                Vs[row*65 + c + 1] = vv.y;
                Vs[row*65 + c + 2] = vv.z;
                Vs[row*65 + c + 3] = vv.w;
            }
        }
        __syncthreads();

        // S = Q K^T  (64x64, k-dim = D = 64)
        float s[4][4] = {};
        #pragma unroll 8
        for (int d = 0; d < 64; d++) {
            float qv[4], kk[4];
            #pragma unroll
            for (int i = 0; i < 4; i++) qv[i] = Qs[(ty*4+i)*65 + d];
            #pragma unroll
            for (int j = 0; j < 4; j++) kk[j] = KPs[(tx*4+j)*65 + d];
            #pragma unroll
            for (int i = 0; i < 4; i++)
                #pragma unroll
                for (int j = 0; j < 4; j++)
                    s[i][j] += qv[i] * kk[j];
        }

        const float scale = 0.125f;   // 1/sqrt(64)
        if (kt == qt) {
            #pragma unroll
            for (int i = 0; i < 4; i++)
                #pragma unroll
                for (int j = 0; j < 4; j++) {
                    const int qg = ty*4 + i, kg = tx*4 + j;
                    s[i][j] = (kg <= qg) ? s[i][j] * scale : -1e30f;
                }
        } else {
            #pragma unroll
            for (int i = 0; i < 4; i++)
                #pragma unroll
                for (int j = 0; j < 4; j++)
                    s[i][j] *= scale;
        }

        // Online softmax
        float nm[4], rs[4];
        #pragma unroll
        for (int i = 0; i < 4; i++) {
            float rm = fmaxf(fmaxf(s[i][0], s[i][1]), fmaxf(s[i][2], s[i][3]));
            #pragma unroll
            for (int o = 8; o >= 1; o >>= 1)
                rm = fmaxf(rm, __shfl_xor_sync(0xffffffffu, rm, o));
            nm[i] = fmaxf(mi[i], rm);
        }
        #pragma unroll
        for (int i = 0; i < 4; i++) {
            float sum = 0.0f;
            #pragma unroll
            for (int j = 0; j < 4; j++) {
                s[i][j] = __expf(s[i][j] - nm[i]);
                sum += s[i][j];
            }
            #pragma unroll
            for (int o = 8; o >= 1; o >>= 1)
                sum += __shfl_xor_sync(0xffffffffu, sum, o);
            rs[i] = sum;
        }
        #pragma unroll
        for (int i = 0; i < 4; i++) {
            const float corr = __expf(mi[i] - nm[i]);
            li[i] = li[i] * corr + rs[i];
            mi[i] = nm[i];
            #pragma unroll
            for (int j = 0; j < 4; j++) acc[i][j] *= corr;
        }

        __syncthreads();   // all threads done reading K tile
        // P -> shared (reusing K buffer)
        #pragma unroll
        for (int i = 0; i < 4; i++)
            #pragma unroll
            for (int j = 0; j < 4; j++)
                KPs[(ty*4+i)*65 + tx*4 + j] = s[i][j];
        __syncthreads();

        // acc += P V   (k-dim = 64 kv positions)
        #pragma unroll 8
        for (int kv = 0; kv < 64; kv++) {
            float pv[4], vv[4];
            #pragma unroll
            for (int i = 0; i < 4; i++) pv[i] = KPs[(ty*4+i)*65 + kv];
            #pragma unroll
            for (int j = 0; j < 4; j++) vv[j] = Vs[kv*65 + tx*4 + j];
            #pragma unroll
            for (int i = 0; i < 4; i++)
                #pragma unroll
                for (int j = 0; j < 4; j++)
                    acc[i][j] += pv[i] * vv[j];
        }
    }

    // Epilogue: normalize and write y[b, t, h*D + d]
    #pragma unroll
    for (int i = 0; i < 4; i++) {
        const float inv = 1.0f / li[i];
        const int t = q0 + ty*4 + i;
        float4 o;
        o.x = acc[i][0] * inv;
        o.y = acc[i][1] * inv;
        o.z = acc[i][2] * inv;
        o.w = acc[i][3] * inv;
        *(float4*)(g_Y + ((size_t)b*T_ + t)*C_ + h*D_ + tx*4) = o;
    }
}

// ---------------------------------------------------------------------------
extern "C" void kernel_launch(void* const* d_in, const int* in_sizes, int n_in,
                              void* d_out, int out_size)
{
    const float* x  = (const float*)d_in[0];
    const float* Wq = (const float*)d_in[1];
    const float* Wk = (const float*)d_in[2];
    const float* Wv = (const float*)d_in[3];
    const float* Wo = (const float*)d_in[4];
    float* out = (float*)d_out;

    float *qp, *kp, *vp, *yp;
    cudaGetSymbolAddress((void**)&qp, g_Q);
    cudaGetSymbolAddress((void**)&kp, g_K);
    cudaGetSymbolAddress((void**)&vp, g_V);
    cudaGetSymbolAddress((void**)&yp, g_Y);

    const dim3 gp(C_/64, M_/64);   // (16, 64)
    proj_kernel<0><<<gp, 256>>>(x, Wq, qp);
    proj_kernel<0><<<gp, 256>>>(x, Wk, kp);
    proj_kernel<0><<<gp, 256>>>(x, Wv, vp);

    const int smem = 3 * 64 * 65 * (int)sizeof(float);   // 49920 B
    cudaFuncSetAttribute(attn_kernel,
                         cudaFuncAttributeMaxDynamicSharedMemorySize, smem);
    attn_kernel<<<dim3(T_/64, B_*H_), 256, smem>>>();

    proj_kernel<1><<<gp, 256>>>(yp, Wo, out);
}

// round 3
// speedup vs baseline: 1.5222x; 1.5222x over previous
#include <cuda_runtime.h>
#include <cuda_bf16.h>
#include <math.h>
#include <cstdint>

#define B_ 2
#define T_ 2048
#define C_ 1024
#define H_ 16
#define D_ 64
#define M_ (B_*T_)   // 4096

// Scratch (device globals -- allocation-free)
__device__ float g_Q[B_*H_*T_*D_];
__device__ float g_K[B_*H_*T_*D_];
__device__ float g_V[B_*H_*T_*D_];
__device__ float g_Y[B_*T_*C_];

extern __shared__ char dynsmem[];

// ===========================================================================
// mma.sync helpers (portable sm_80+ path; works on base sm_100)
// ===========================================================================
__device__ __forceinline__ uint32_t smem_u32(const void* p) {
    uint32_t a;
    asm("{ .reg .u64 t; cvta.to.shared.u64 t, %1; cvt.u32.u64 %0, t; }"
        : "=r"(a) : "l"(p));
    return a;
}
__device__ __forceinline__ void ldm_x4(uint32_t r[4], uint32_t addr) {
    asm volatile("ldmatrix.sync.aligned.m8n8.x4.shared.b16 {%0,%1,%2,%3}, [%4];"
                 : "=r"(r[0]), "=r"(r[1]), "=r"(r[2]), "=r"(r[3]) : "r"(addr));
}
__device__ __forceinline__ void mma16816(float c[4], const uint32_t a[4],
                                         const uint32_t b[2]) {
    asm volatile(
        "mma.sync.aligned.m16n8k16.row.col.f32.bf16.bf16.f32 "
        "{%0,%1,%2,%3}, {%4,%5,%6,%7}, {%8,%9}, {%0,%1,%2,%3};"
        : "+f"(c[0]), "+f"(c[1]), "+f"(c[2]), "+f"(c[3])
        : "r"(a[0]), "r"(a[1]), "r"(a[2]), "r"(a[3]), "r"(b[0]), "r"(b[1]));
}
__device__ __forceinline__ uint32_t packbf(__nv_bfloat16 a, __nv_bfloat16 b) {
    return (uint32_t)__bfloat16_as_ushort(a)
         | ((uint32_t)__bfloat16_as_ushort(b) << 16);
}
__device__ __forceinline__ void split4(float4 v, uint2& hi, uint2& lo) {
    __nv_bfloat16 h0 = __float2bfloat16(v.x), h1 = __float2bfloat16(v.y);
    __nv_bfloat16 h2 = __float2bfloat16(v.z), h3 = __float2bfloat16(v.w);
    float r0 = v.x - __bfloat162float(h0), r1 = v.y - __bfloat162float(h1);
    float r2 = v.z - __bfloat162float(h2), r3 = v.w - __bfloat162float(h3);
    hi.x = packbf(h0, h1); hi.y = packbf(h2, h3);
    lo.x = packbf(__float2bfloat16(r0), __float2bfloat16(r1));
    lo.y = packbf(__float2bfloat16(r2), __float2bfloat16(r3));
}

// ===========================================================================
// Projection GEMM via mma.sync bf16x3 split.
// out[m,n] = sum_k X[m,k] * W[n,k].  CTA tile 128x128, K-block 32, 2 stages.
// 8 warps: warp_m = wid&1 (64 rows), warp_n = wid>>1 (32 cols).
// MODE 0: scatter to [B,H,T,D] (3 matrices fused, grid.x = 24)
// MODE 1: plain [M,N]          (grid.x = 8)
// ===========================================================================
#define LDKE  40                      // smem row pitch in bf16 elems (80 B)
#define PTILE (128*LDKE)              // one operand tile, elems
#define PROJ_SMEM (2*4*PTILE*2)       // 2 stages * 4 tiles * bf16 = 81920 B

template<int MODE>
__global__ void __launch_bounds__(256) proj_mma(
    const float* __restrict__ X,
    const float* __restrict__ W0, const float* __restrict__ W1,
    const float* __restrict__ W2,
    float* __restrict__ O0, float* __restrict__ O1, float* __restrict__ O2)
{
    __nv_bfloat16* sb = (__nv_bfloat16*)dynsmem;
    const uint32_t sbu = smem_u32(sb);

    const int tid  = threadIdx.x;
    const int wid  = tid >> 5, lane = tid & 31;
    const int wm   = wid & 1,  wn   = wid >> 1;
    const int mat  = blockIdx.x >> 3;
    const int bn   = (blockIdx.x & 7) * 128;
    const int bm   = blockIdx.y * 128;

    const float* W = (mat == 0) ? W0 : (mat == 1 ? W1 : W2);
    float*       O = (mat == 0) ? O0 : (mat == 1 ? O1 : O2);

    // ldmatrix per-lane element offsets
    const int qd  = lane >> 3;
    const int rA  = (lane & 7) + (qd & 1) * 8;
    const int cA  = (qd >> 1) * 8;
    const int aoff = (wm * 64 + rA) * LDKE + cA;          // + mi*16*LDKE + ks*16
    const int rB  = (lane & 7) + (qd >> 1) * 8;
    const int cB  = (qd & 1) * 8;
    const int boff = (wn * 32 + rB) * LDKE + cB;          // + np*16*LDKE + ks*16

    // global load mapping: 4 float4 each for X and W per K-block
    const int r0 = tid >> 3;          // 0..31
    const int kg = tid & 7;           // 0..7 (16B group)
    const float* xp = X + (size_t)(bm + r0) * C_ + kg * 4;
    const float* wp = W + (size_t)(bn + r0) * C_ + kg * 4;
    const int sbase = r0 * LDKE + kg * 4;                  // elem offset, +32*i rows

    float acc[4][4][4] = {};

    const int NKB = C_ / 32;          // 32 K-blocks
    float4 xr[4], wr[4];

    // prologue: stage 0
    #pragma unroll
    for (int i = 0; i < 4; i++) {
        xr[i] = *(const float4*)(xp + (size_t)(32 * i) * C_);
        wr[i] = *(const float4*)(wp + (size_t)(32 * i) * C_);
    }
    #pragma unroll
    for (int i = 0; i < 4; i++) {
        uint2 hi, lo;
        const int off = sbase + 32 * i * LDKE;
        split4(xr[i], hi, lo);
        *(uint2*)(sb + off)             = hi;   // XH stage0
        *(uint2*)(sb + off + PTILE)     = lo;   // XL
        split4(wr[i], hi, lo);
        *(uint2*)(sb + off + 2*PTILE)   = hi;   // WH
        *(uint2*)(sb + off + 3*PTILE)   = lo;   // WL
    }
    __syncthreads();

    for (int kb = 0; kb < NKB; kb++) {
        const int cur = kb & 1;
        if (kb + 1 < NKB) {
            const int ko = (kb + 1) * 32;
            #pragma unroll
            for (int i = 0; i < 4; i++) {
                xr[i] = *(const float4*)(xp + (size_t)(32 * i) * C_ + ko);
                wr[i] = *(const float4*)(wp + (size_t)(32 * i) * C_ + ko);
            }
        }

        // compute from stage `cur`
        const uint32_t st = sbu + (uint32_t)(cur * 4 * PTILE) * 2;
        const uint32_t xh = st,               xl = st + PTILE * 2;
        const uint32_t wh = st + 2*PTILE*2,   wl = st + 3*PTILE*2;
        #pragma unroll
        for (int ks = 0; ks < 2; ks++) {
            const int kso = ks * 16;
            uint32_t Ah[4][4], Bh[2][4];
            #pragma unroll
            for (int mi = 0; mi < 4; mi++)
                ldm_x4(Ah[mi], xh + (uint32_t)(aoff + mi*16*LDKE + kso) * 2);
            #pragma unroll
            for (int np = 0; np < 2; np++)
                ldm_x4(Bh[np], wh + (uint32_t)(boff + np*16*LDKE + kso) * 2);
            #pragma unroll
            for (int mi = 0; mi < 4; mi++)
                #pragma unroll
                for (int ni = 0; ni < 4; ni++)
                    mma16816(acc[mi][ni], Ah[mi], &Bh[ni>>1][(ni&1)*2]);

            uint32_t Bl[2][4];
            #pragma unroll
            for (int np = 0; np < 2; np++)
                ldm_x4(Bl[np], wl + (uint32_t)(boff + np*16*LDKE + kso) * 2);
            #pragma unroll
            for (int mi = 0; mi < 4; mi++)
                #pragma unroll
                for (int ni = 0; ni < 4; ni++)
                    mma16816(acc[mi][ni], Ah[mi], &Bl[ni>>1][(ni&1)*2]);

            uint32_t Al[4][4];
            #pragma unroll
            for (int mi = 0; mi < 4; mi++)
                ldm_x4(Al[mi], xl + (uint32_t)(aoff + mi*16*LDKE + kso) * 2);
            #pragma unroll
            for (int mi = 0; mi < 4; mi++)
                #pragma unroll
                for (int ni = 0; ni < 4; ni++)
                    mma16816(acc[mi][ni], Al[mi], &Bh[ni>>1][(ni&1)*2]);
        }

        if (kb + 1 < NKB) {
            __nv_bfloat16* nst = sb + ((kb + 1) & 1) * 4 * PTILE;
            #pragma unroll
            for (int i = 0; i < 4; i++) {
                uint2 hi, lo;
                const int off = sbase + 32 * i * LDKE;
                split4(xr[i], hi, lo);
                *(uint2*)(nst + off)           = hi;
                *(uint2*)(nst + off + PTILE)   = lo;
                split4(wr[i], hi, lo);
                *(uint2*)(nst + off + 2*PTILE) = hi;
                *(uint2*)(nst + off + 3*PTILE) = lo;
            }
        }
        __syncthreads();
    }

    // epilogue
    const int g  = lane >> 2;
    const int i2 = (lane & 3) * 2;
    #pragma unroll
    for (int mi = 0; mi < 4; mi++) {
        #pragma unroll
        for (int ni = 0; ni < 4; ni++) {
            const int col = bn + wn * 32 + ni * 8 + i2;
            #pragma unroll
            for (int half = 0; half < 2; half++) {
                const int m = bm + wm * 64 + mi * 16 + g + half * 8;
                float2 v = make_float2(acc[mi][ni][half*2], acc[mi][ni][half*2+1]);
                if (MODE == 0) {
                    const int b = m >> 11, t = m & (T_ - 1);
                    const int h = col >> 6, d = col & 63;
                    *(float2*)(O + (((size_t)(b*H_ + h) * T_ + t) << 6) + d) = v;
                } else {
                    *(float2*)(O + (size_t)m * C_ + col) = v;
                }
            }
        }
    }
}

// ---------------------------------------------------------------------------
// Flash attention (unchanged from R1): fp32 SIMT, causal, 64x64 tiles.
// ---------------------------------------------------------------------------
__global__ void __launch_bounds__(256) attn_kernel()
{
    float* sm  = (float*)dynsmem;
    float* Qs  = sm;
    float* KPs = sm + 64*65;
    float* Vs  = sm + 2*64*65;

    const int bh = blockIdx.y;
    const int qt = gridDim.x - 1 - blockIdx.x;
    const int b  = bh >> 4;
    const int h  = bh & 15;
    const float* Qg = g_Q + (size_t)bh * (T_*D_);
    const float* Kg = g_K + (size_t)bh * (T_*D_);
    const float* Vg = g_V + (size_t)bh * (T_*D_);
    const int q0 = qt * 64;
    const int tid = threadIdx.x;
    const int ty = tid >> 4, tx = tid & 15;

    {
        const int r = tid >> 4;
        const int c = (tid & 15) * 4;
        #pragma unroll
        for (int it = 0; it < 4; it++) {
            const int row = r + it*16;
            float4 v = *(const float4*)(Qg + (q0 + row)*D_ + c);
            Qs[row*65 + c + 0] = v.x; Qs[row*65 + c + 1] = v.y;
            Qs[row*65 + c + 2] = v.z; Qs[row*65 + c + 3] = v.w;
        }
    }

    float acc[4][4] = {};
    float mi[4], li[4];
    #pragma unroll
    for (int i = 0; i < 4; i++) { mi[i] = -1e30f; li[i] = 0.0f; }

    for (int kt = 0; kt <= qt; kt++) {
        __syncthreads();
        {
            const int r = tid >> 4;
            const int c = (tid & 15) * 4;
            #pragma unroll
            for (int it = 0; it < 4; it++) {
                const int row = r + it*16;
                float4 kv = *(const float4*)(Kg + (kt*64 + row)*D_ + c);
                KPs[row*65 + c + 0] = kv.x; KPs[row*65 + c + 1] = kv.y;
                KPs[row*65 + c + 2] = kv.z; KPs[row*65 + c + 3] = kv.w;
                float4 vv = *(const float4*)(Vg + (kt*64 + row)*D_ + c);
                Vs[row*65 + c + 0] = vv.x; Vs[row*65 + c + 1] = vv.y;
                Vs[row*65 + c + 2] = vv.z; Vs[row*65 + c + 3] = vv.w;
            }
        }
        __syncthreads();

        float s[4][4] = {};
        #pragma unroll 8
        for (int d = 0; d < 64; d++) {
            float qv[4], kk[4];
            #pragma unroll
            for (int i = 0; i < 4; i++) qv[i] = Qs[(ty*4+i)*65 + d];
            #pragma unroll
            for (int j = 0; j < 4; j++) kk[j] = KPs[(tx*4+j)*65 + d];
            #pragma unroll
            for (int i = 0; i < 4; i++)
                #pragma unroll
                for (int j = 0; j < 4; j++)
                    s[i][j] += qv[i] * kk[j];
        }

        const float scale = 0.125f;
        if (kt == qt) {
            #pragma unroll
            for (int i = 0; i < 4; i++)
                #pragma unroll
                for (int j = 0; j < 4; j++) {
                    const int qg = ty*4 + i, kg = tx*4 + j;
                    s[i][j] = (kg <= qg) ? s[i][j] * scale : -1e30f;
                }
        } else {
            #pragma unroll
            for (int i = 0; i < 4; i++)
                #pragma unroll
                for (int j = 0; j < 4; j++)
                    s[i][j] *= scale;
        }

        float nm[4], rs[4];
        #pragma unroll
        for (int i = 0; i < 4; i++) {
            float rm = fmaxf(fmaxf(s[i][0], s[i][1]), fmaxf(s[i][2], s[i][3]));
            #pragma unroll
            for (int o = 8; o >= 1; o >>= 1)
                rm = fmaxf(rm, __shfl_xor_sync(0xffffffffu, rm, o));
            nm[i] = fmaxf(mi[i], rm);
        }
        #pragma unroll
        for (int i = 0; i < 4; i++) {
            float sum = 0.0f;
            #pragma unroll
            for (int j = 0; j < 4; j++) {
                s[i][j] = __expf(s[i][j] - nm[i]);
                sum += s[i][j];
            }
            #pragma unroll
            for (int o = 8; o >= 1; o >>= 1)
                sum += __shfl_xor_sync(0xffffffffu, sum, o);
            rs[i] = sum;
        }
        #pragma unroll
        for (int i = 0; i < 4; i++) {
            const float corr = __expf(mi[i] - nm[i]);
            li[i] = li[i] * corr + rs[i];
            mi[i] = nm[i];
            #pragma unroll
            for (int j = 0; j < 4; j++) acc[i][j] *= corr;
        }

        __syncthreads();
        #pragma unroll
        for (int i = 0; i < 4; i++)
            #pragma unroll
            for (int j = 0; j < 4; j++)
                KPs[(ty*4+i)*65 + tx*4 + j] = s[i][j];
        __syncthreads();

        #pragma unroll 8
        for (int kv = 0; kv < 64; kv++) {
            float pv[4], vv[4];
            #pragma unroll
            for (int i = 0; i < 4; i++) pv[i] = KPs[(ty*4+i)*65 + kv];
            #pragma unroll
            for (int j = 0; j < 4; j++) vv[j] = Vs[kv*65 + tx*4 + j];
            #pragma unroll
            for (int i = 0; i < 4; i++)
                #pragma unroll
                for (int j = 0; j < 4; j++)
                    acc[i][j] += pv[i] * vv[j];
        }
    }

    #pragma unroll
    for (int i = 0; i < 4; i++) {
        const float inv = 1.0f / li[i];
        const int t = q0 + ty*4 + i;
        float4 o;
        o.x = acc[i][0] * inv; o.y = acc[i][1] * inv;
        o.z = acc[i][2] * inv; o.w = acc[i][3] * inv;
        *(float4*)(g_Y + ((size_t)b*T_ + t)*C_ + h*D_ + tx*4) = o;
    }
}

// ---------------------------------------------------------------------------
extern "C" void kernel_launch(void* const* d_in, const int* in_sizes, int n_in,
                              void* d_out, int out_size)
{
    const float* x  = (const float*)d_in[0];
    const float* Wq = (const float*)d_in[1];
    const float* Wk = (const float*)d_in[2];
    const float* Wv = (const float*)d_in[3];
    const float* Wo = (const float*)d_in[4];
    float* out = (float*)d_out;

    float *qp, *kp, *vp, *yp;
    cudaGetSymbolAddress((void**)&qp, g_Q);
    cudaGetSymbolAddress((void**)&kp, g_K);
    cudaGetSymbolAddress((void**)&vp, g_V);
    cudaGetSymbolAddress((void**)&yp, g_Y);

    cudaFuncSetAttribute(proj_mma<0>, cudaFuncAttributeMaxDynamicSharedMemorySize,
                         PROJ_SMEM);
    cudaFuncSetAttribute(proj_mma<1>, cudaFuncAttributeMaxDynamicSharedMemorySize,
                         PROJ_SMEM);

    // fused QKV: grid.x = 3 mats * 8 n-tiles
    proj_mma<0><<<dim3(24, M_/128), 256, PROJ_SMEM>>>(x, Wq, Wk, Wv, qp, kp, vp);

    const int smem = 3 * 64 * 65 * (int)sizeof(float);   // 49920 B
    cudaFuncSetAttribute(attn_kernel,
                         cudaFuncAttributeMaxDynamicSharedMemorySize, smem);
    attn_kernel<<<dim3(T_/64, B_*H_), 256, smem>>>();

    proj_mma<1><<<dim3(8, M_/128), 256, PROJ_SMEM>>>(yp, Wo, Wo, Wo, out, out, out);
}

// round 4
// speedup vs baseline: 2.9448x; 1.9345x over previous
#include <cuda_runtime.h>
#include <cuda_bf16.h>
#include <cuda_fp16.h>
#include <math.h>
#include <cstdint>

#define B_ 2
#define T_ 2048
#define C_ 1024
#define H_ 16
#define D_ 64
#define M_ (B_*T_)   // 4096

// Scratch (device globals -- allocation-free)
__device__ __half g_Qh[B_*H_*T_*D_];   // Q * 0.125, fp16 hi
__device__ __half g_Ql[B_*H_*T_*D_];   // Q * 0.125, fp16 residual
__device__ __half g_Kh[B_*H_*T_*D_];   // K fp16
__device__ __half g_Vh[B_*H_*T_*D_];   // V fp16
__device__ float  g_Y [B_*T_*C_];

extern __shared__ char dynsmem[];

// ===========================================================================
// helpers
// ===========================================================================
__device__ __forceinline__ uint32_t smem_u32(const void* p) {
    uint32_t a;
    asm("{ .reg .u64 t; cvta.to.shared.u64 t, %1; cvt.u32.u64 %0, t; }"
        : "=r"(a) : "l"(p));
    return a;
}
__device__ __forceinline__ void ldm_x4(uint32_t r[4], uint32_t addr) {
    asm volatile("ldmatrix.sync.aligned.m8n8.x4.shared.b16 {%0,%1,%2,%3}, [%4];"
                 : "=r"(r[0]), "=r"(r[1]), "=r"(r[2]), "=r"(r[3]) : "r"(addr));
}
__device__ __forceinline__ void ldm_x4_t(uint32_t r[4], uint32_t addr) {
    asm volatile("ldmatrix.sync.aligned.m8n8.x4.trans.shared.b16 {%0,%1,%2,%3}, [%4];"
                 : "=r"(r[0]), "=r"(r[1]), "=r"(r[2]), "=r"(r[3]) : "r"(addr));
}
__device__ __forceinline__ void mma_bf(float c[4], const uint32_t a[4],
                                       const uint32_t b[2]) {
    asm volatile(
        "mma.sync.aligned.m16n8k16.row.col.f32.bf16.bf16.f32 "
        "{%0,%1,%2,%3}, {%4,%5,%6,%7}, {%8,%9}, {%0,%1,%2,%3};"
        : "+f"(c[0]), "+f"(c[1]), "+f"(c[2]), "+f"(c[3])
        : "r"(a[0]), "r"(a[1]), "r"(a[2]), "r"(a[3]), "r"(b[0]), "r"(b[1]));
}
__device__ __forceinline__ void mma_fp(float c[4], const uint32_t a[4],
                                       const uint32_t b[2]) {
    asm volatile(
        "mma.sync.aligned.m16n8k16.row.col.f32.f16.f16.f32 "
        "{%0,%1,%2,%3}, {%4,%5,%6,%7}, {%8,%9}, {%0,%1,%2,%3};"
        : "+f"(c[0]), "+f"(c[1]), "+f"(c[2]), "+f"(c[3])
        : "r"(a[0]), "r"(a[1]), "r"(a[2]), "r"(a[3]), "r"(b[0]), "r"(b[1]));
}
__device__ __forceinline__ uint32_t packbf(__nv_bfloat16 a, __nv_bfloat16 b) {
    return (uint32_t)__bfloat16_as_ushort(a)
         | ((uint32_t)__bfloat16_as_ushort(b) << 16);
}
__device__ __forceinline__ uint32_t packh(__half a, __half b) {
    return (uint32_t)__half_as_ushort(a)
         | ((uint32_t)__half_as_ushort(b) << 16);
}
__device__ __forceinline__ void split4(float4 v, uint2& hi, uint2& lo) {
    __nv_bfloat16 h0 = __float2bfloat16(v.x), h1 = __float2bfloat16(v.y);
    __nv_bfloat16 h2 = __float2bfloat16(v.z), h3 = __float2bfloat16(v.w);
    float r0 = v.x - __bfloat162float(h0), r1 = v.y - __bfloat162float(h1);
    float r2 = v.z - __bfloat162float(h2), r3 = v.w - __bfloat162float(h3);
    hi.x = packbf(h0, h1); hi.y = packbf(h2, h3);
    lo.x = packbf(__float2bfloat16(r0), __float2bfloat16(r1));
    lo.y = packbf(__float2bfloat16(r2), __float2bfloat16(r3));
}
__device__ __forceinline__ void psplit(float a, float b, uint32_t& hi, uint32_t& lo) {
    __half h0 = __float2half_rn(a), h1 = __float2half_rn(b);
    hi = packh(h0, h1);
    lo = packh(__float2half_rn(a - __half2float(h0)),
               __float2half_rn(b - __half2float(h1)));
}
__device__ __forceinline__ void cpa16(uint32_t dst, const void* src) {
    asm volatile("cp.async.cg.shared.global [%0], [%1], 16;" :: "r"(dst), "l"(src));
}
#define CP_COMMIT()  asm volatile("cp.async.commit_group;" ::: "memory")
#define CP_WAIT0()   asm volatile("cp.async.wait_group 0;" ::: "memory")
#define CP_WAIT1()   asm volatile("cp.async.wait_group 1;" ::: "memory")

// ===========================================================================
// Projection GEMM via mma.sync bf16x3 split (unchanged core from R3).
// MODE 0: fused QKV -> fp16 scratch (Q scaled+split; K,V single fp16)
// MODE 1: plain fp32 [M,N] out
// ===========================================================================
#define LDKE  40
#define PTILE (128*LDKE)
#define PROJ_SMEM (2*4*PTILE*2)

template<int MODE>
__global__ void __launch_bounds__(256) proj_mma(
    const float* __restrict__ X,
    const float* __restrict__ W0, const float* __restrict__ W1,
    const float* __restrict__ W2,
    float* __restrict__ fout)
{
    __nv_bfloat16* sb = (__nv_bfloat16*)dynsmem;
    const uint32_t sbu = smem_u32(sb);

    const int tid  = threadIdx.x;
    const int wid  = tid >> 5, lane = tid & 31;
    const int wm   = wid & 1,  wn   = wid >> 1;
    const int mat  = blockIdx.x >> 3;
    const int bn   = (blockIdx.x & 7) * 128;
    const int bm   = blockIdx.y * 128;

    const float* W = (mat == 0) ? W0 : (mat == 1 ? W1 : W2);

    const int qd  = lane >> 3;
    const int rA  = (lane & 7) + (qd & 1) * 8;
    const int cA  = (qd >> 1) * 8;
    const int aoff = (wm * 64 + rA) * LDKE + cA;
    const int rB  = (lane & 7) + (qd >> 1) * 8;
    const int cB  = (qd & 1) * 8;
    const int boff = (wn * 32 + rB) * LDKE + cB;

    const int r0 = tid >> 3;
    const int kg = tid & 7;
    const float* xp = X + (size_t)(bm + r0) * C_ + kg * 4;
    const float* wp = W + (size_t)(bn + r0) * C_ + kg * 4;
    const int sbase = r0 * LDKE + kg * 4;

    float acc[4][4][4] = {};
    const int NKB = C_ / 32;
    float4 xr[4], wr[4];

    #pragma unroll
    for (int i = 0; i < 4; i++) {
        xr[i] = *(const float4*)(xp + (size_t)(32 * i) * C_);
        wr[i] = *(const float4*)(wp + (size_t)(32 * i) * C_);
    }
    #pragma unroll
    for (int i = 0; i < 4; i++) {
        uint2 hi, lo;
        const int off = sbase + 32 * i * LDKE;
        split4(xr[i], hi, lo);
        *(uint2*)(sb + off)             = hi;
        *(uint2*)(sb + off + PTILE)     = lo;
        split4(wr[i], hi, lo);
        *(uint2*)(sb + off + 2*PTILE)   = hi;
        *(uint2*)(sb + off + 3*PTILE)   = lo;
    }
    __syncthreads();

    for (int kb = 0; kb < NKB; kb++) {
        const int cur = kb & 1;
        if (kb + 1 < NKB) {
            const int ko = (kb + 1) * 32;
            #pragma unroll
            for (int i = 0; i < 4; i++) {
                xr[i] = *(const float4*)(xp + (size_t)(32 * i) * C_ + ko);
                wr[i] = *(const float4*)(wp + (size_t)(32 * i) * C_ + ko);
            }
        }
        const uint32_t st = sbu + (uint32_t)(cur * 4 * PTILE) * 2;
        const uint32_t xh = st,               xl = st + PTILE * 2;
        const uint32_t wh = st + 2*PTILE*2,   wl = st + 3*PTILE*2;
        #pragma unroll
        for (int ks = 0; ks < 2; ks++) {
            const int kso = ks * 16;
            uint32_t Ah[4][4], Bh[2][4];
            #pragma unroll
            for (int mi = 0; mi < 4; mi++)
                ldm_x4(Ah[mi], xh + (uint32_t)(aoff + mi*16*LDKE + kso) * 2);
            #pragma unroll
            for (int np = 0; np < 2; np++)
                ldm_x4(Bh[np], wh + (uint32_t)(boff + np*16*LDKE + kso) * 2);
            #pragma unroll
            for (int mi = 0; mi < 4; mi++)
                #pragma unroll
                for (int ni = 0; ni < 4; ni++)
                    mma_bf(acc[mi][ni], Ah[mi], &Bh[ni>>1][(ni&1)*2]);

            uint32_t Bl[2][4];
            #pragma unroll
            for (int np = 0; np < 2; np++)
                ldm_x4(Bl[np], wl + (uint32_t)(boff + np*16*LDKE + kso) * 2);
            #pragma unroll
            for (int mi = 0; mi < 4; mi++)
                #pragma unroll
                for (int ni = 0; ni < 4; ni++)
                    mma_bf(acc[mi][ni], Ah[mi], &Bl[ni>>1][(ni&1)*2]);

            uint32_t Al[4][4];
            #pragma unroll
            for (int mi = 0; mi < 4; mi++)
                ldm_x4(Al[mi], xl + (uint32_t)(aoff + mi*16*LDKE + kso) * 2);
            #pragma unroll
            for (int mi = 0; mi < 4; mi++)
                #pragma unroll
                for (int ni = 0; ni < 4; ni++)
                    mma_bf(acc[mi][ni], Al[mi], &Bh[ni>>1][(ni&1)*2]);
        }

        if (kb + 1 < NKB) {
            __nv_bfloat16* nst = sb + ((kb + 1) & 1) * 4 * PTILE;
            #pragma unroll
            for (int i = 0; i < 4; i++) {
                uint2 hi, lo;
                const int off = sbase + 32 * i * LDKE;
                split4(xr[i], hi, lo);
                *(uint2*)(nst + off)           = hi;
                *(uint2*)(nst + off + PTILE)   = lo;
                split4(wr[i], hi, lo);
                *(uint2*)(nst + off + 2*PTILE) = hi;
                *(uint2*)(nst + off + 3*PTILE) = lo;
            }
        }
        __syncthreads();
    }

    // epilogue
    const int g  = lane >> 2;
    const int i2 = (lane & 3) * 2;
    #pragma unroll
    for (int mi = 0; mi < 4; mi++) {
        #pragma unroll
        for (int ni = 0; ni < 4; ni++) {
            const int col = bn + wn * 32 + ni * 8 + i2;
            #pragma unroll
            for (int half = 0; half < 2; half++) {
                const int m = bm + wm * 64 + mi * 16 + g + half * 8;
                const float vx = acc[mi][ni][half*2], vy = acc[mi][ni][half*2+1];
                if (MODE == 0) {
                    const int b = m >> 11, t = m & (T_ - 1);
                    const int h = col >> 6, d = col & 63;
                    const size_t idx = (((size_t)(b*H_ + h) * T_ + t) << 6) + d;
                    if (mat == 0) {
                        const float s0 = vx * 0.125f, s1 = vy * 0.125f;
                        const __half h0 = __float2half_rn(s0);
                        const __half h1 = __float2half_rn(s1);
                        *(uint32_t*)(g_Qh + idx) = packh(h0, h1);
                        *(uint32_t*)(g_Ql + idx) = packh(
                            __float2half_rn(s0 - __half2float(h0)),
                            __float2half_rn(s1 - __half2float(h1)));
                    } else if (mat == 1) {
                        *(uint32_t*)(g_Kh + idx) =
                            packh(__float2half_rn(vx), __float2half_rn(vy));
                    } else {
                        *(uint32_t*)(g_Vh + idx) =
                            packh(__float2half_rn(vx), __float2half_rn(vy));
                    }
                } else {
                    *(float2*)(fout + (size_t)m * C_ + col) = make_float2(vx, vy);
                }
            }
        }
    }
}

// ===========================================================================
// Flash attention on mma.sync fp16.  BQ=128, BK=64, 8 warps (16 q-rows each).
// S = (Qh+Ql)*K ; O = (Ph+Pl)*V ; P register-reused as A-fragment.
// ===========================================================================
#define AT_PB   144                 // smem row pitch bytes (72 halfs)
#define AT_KV   (64*AT_PB)          // one 64-row tile = 9216 B
#define AT_STG  (2*AT_KV)           // K+V per stage = 18432 B
#define AT_SMEM (2*AT_STG)          // 36864 B

__global__ void __launch_bounds__(256) attn_mma()
{
    char* sm = dynsmem;
    const uint32_t sb = smem_u32(sm);
    const int tid  = threadIdx.x;
    const int wid  = tid >> 5, lane = tid & 31;
    const int bh   = blockIdx.y;
    const int qt   = gridDim.x - 1 - blockIdx.x;    // heavy-first
    const int q0   = qt * 128;

    const size_t base = (size_t)bh * (T_ * D_);
    const __half* Qhg = g_Qh + base + (size_t)q0 * D_;
    const __half* Qlg = g_Ql + base + (size_t)q0 * D_;
    const __half* Kg  = g_Kh + base;
    const __half* Vg  = g_Vh + base;

    // ---- stage Q (128 rows x 64 halfs, hi+lo) into smem, ldmatrix to regs
    {
        #pragma unroll
        for (int i = 0; i < 8; i++) {
            const int c   = tid + i * 256;     // 0..2047
            const int arr = c >> 10;           // 0 = hi, 1 = lo
            const int g1  = c & 1023;
            const int r   = g1 >> 3;
            const int ch  = g1 & 7;
            const uint4 v = *(const uint4*)((arr ? Qlg : Qhg) + r * 64 + ch * 8);
            *(uint4*)(sm + arr * AT_STG + r * AT_PB + ch * 16) = v;
        }
    }
    __syncthreads();

    uint32_t qfh[4][4], qfl[4][4];
    {
        const uint32_t qb = sb + (uint32_t)((wid * 16 + (lane & 15)) * AT_PB
                                            + (lane >> 4) * 16);
        #pragma unroll
        for (int ks = 0; ks < 4; ks++) {
            ldm_x4(qfh[ks], qb + ks * 32);
            ldm_x4(qfl[ks], qb + AT_STG + ks * 32);
        }
    }
    __syncthreads();

    float S[8][4];
    float O[8][4] = {};
    float mi[2] = {-1e30f, -1e30f};
    float li[2] = {0.0f, 0.0f};

    const int nkt    = 2 * qt + 2;
    const int maskst = 2 * qt;

    // prefetch helper as lambda
    auto prefetch = [&](int kt, int stg) {
        #pragma unroll
        for (int i = 0; i < 4; i++) {
            const int c   = tid + i * 256;     // 0..1023
            const int arr = c >> 9;            // 0=K, 1=V
            const int g1  = c & 511;
            const int r   = g1 >> 3;
            const int ch  = g1 & 7;
            const __half* src = (arr ? Vg : Kg) + (size_t)(kt * 64 + r) * 64 + ch * 8;
            cpa16(sb + stg * AT_STG + arr * AT_KV + r * AT_PB + ch * 16, src);
        }
    };

    prefetch(0, 0);
    CP_COMMIT();

    for (int kt = 0; kt < nkt; kt++) {
        const int cur = kt & 1;
        if (kt + 1 < nkt) {
            prefetch(kt + 1, cur ^ 1);
            CP_COMMIT();
            CP_WAIT1();
        } else {
            CP_WAIT0();
        }
        __syncthreads();

        const bool active = (kt * 64) <= (q0 + wid * 16 + 15);
        if (active) {
            const uint32_t kb = sb + cur * AT_STG;
            const uint32_t vb = kb + AT_KV;
            const uint32_t lm = (uint32_t)((lane & 15) * AT_PB + (lane >> 4) * 16);

            #pragma unroll
            for (int j = 0; j < 8; j++)
                #pragma unroll
                for (int e = 0; e < 4; e++) S[j][e] = 0.0f;

            // ---- S = Q K^T
            #pragma unroll
            for (int ks = 0; ks < 4; ks++) {
                #pragma unroll
                for (int j16 = 0; j16 < 4; j16++) {
                    uint32_t kf[4];
                    ldm_x4(kf, kb + lm + (uint32_t)(j16 * 16 * AT_PB + ks * 32));
                    uint32_t b0[2] = {kf[0], kf[2]};
                    uint32_t b1[2] = {kf[1], kf[3]};
                    mma_fp(S[2*j16],   qfh[ks], b0);
                    mma_fp(S[2*j16],   qfl[ks], b0);
                    mma_fp(S[2*j16+1], qfh[ks], b1);
                    mma_fp(S[2*j16+1], qfl[ks], b1);
                }
            }

            // ---- causal mask (only the last two tiles)
            if (kt >= maskst) {
                const int qr = q0 + wid * 16 + (lane >> 2);
                const int kcb = kt * 64 + 2 * (lane & 3);
                #pragma unroll
                for (int j = 0; j < 8; j++) {
                    const int kc = kcb + 8 * j;
                    if (kc     > qr)     S[j][0] = -1e30f;
                    if (kc + 1 > qr)     S[j][1] = -1e30f;
                    if (kc     > qr + 8) S[j][2] = -1e30f;
                    if (kc + 1 > qr + 8) S[j][3] = -1e30f;
                }
            }

            // ---- online softmax (2 rows per thread)
            float m0 = -1e30f, m1 = -1e30f;
            #pragma unroll
            for (int j = 0; j < 8; j++) {
                m0 = fmaxf(m0, fmaxf(S[j][0], S[j][1]));
                m1 = fmaxf(m1, fmaxf(S[j][2], S[j][3]));
            }
            m0 = fmaxf(m0, __shfl_xor_sync(0xffffffffu, m0, 1));
            m0 = fmaxf(m0, __shfl_xor_sync(0xffffffffu, m0, 2));
            m1 = fmaxf(m1, __shfl_xor_sync(0xffffffffu, m1, 1));
            m1 = fmaxf(m1, __shfl_xor_sync(0xffffffffu, m1, 2));
            const float nm0 = fmaxf(mi[0], m0);
            const float nm1 = fmaxf(mi[1], m1);
            float s0 = 0.0f, s1 = 0.0f;
            #pragma unroll
            for (int j = 0; j < 8; j++) {
                S[j][0] = __expf(S[j][0] - nm0);
                S[j][1] = __expf(S[j][1] - nm0);
                S[j][2] = __expf(S[j][2] - nm1);
                S[j][3] = __expf(S[j][3] - nm1);
                s0 += S[j][0] + S[j][1];
                s1 += S[j][2] + S[j][3];
            }
            s0 += __shfl_xor_sync(0xffffffffu, s0, 1);
            s0 += __shfl_xor_sync(0xffffffffu, s0, 2);
            s1 += __shfl_xor_sync(0xffffffffu, s1, 1);
            s1 += __shfl_xor_sync(0xffffffffu, s1, 2);
            const float c0 = __expf(mi[0] - nm0);
            const float c1 = __expf(mi[1] - nm1);
            li[0] = li[0] * c0 + s0;  mi[0] = nm0;
            li[1] = li[1] * c1 + s1;  mi[1] = nm1;
            #pragma unroll
            for (int j = 0; j < 8; j++) {
                O[j][0] *= c0; O[j][1] *= c0;
                O[j][2] *= c1; O[j][3] *= c1;
            }

            // ---- O += P V  (P repacked from S fragments, hi+lo)
            #pragma unroll
            for (int j16 = 0; j16 < 4; j16++) {
                uint32_t ph[4], pl[4];
                psplit(S[2*j16][0],   S[2*j16][1],   ph[0], pl[0]);
                psplit(S[2*j16][2],   S[2*j16][3],   ph[1], pl[1]);
                psplit(S[2*j16+1][0], S[2*j16+1][1], ph[2], pl[2]);
                psplit(S[2*j16+1][2], S[2*j16+1][3], ph[3], pl[3]);
                #pragma unroll
                for (int dt = 0; dt < 4; dt++) {
                    uint32_t vf[4];
                    ldm_x4_t(vf, vb + lm + (uint32_t)(j16 * 16 * AT_PB + dt * 32));
                    uint32_t vb0[2] = {vf[0], vf[1]};
                    uint32_t vb1[2] = {vf[2], vf[3]};
                    mma_fp(O[2*dt],   ph, vb0);
                    mma_fp(O[2*dt],   pl, vb0);
                    mma_fp(O[2*dt+1], ph, vb1);
                    mma_fp(O[2*dt+1], pl, vb1);
                }
            }
        }
        __syncthreads();
    }

    // ---- epilogue: normalize, write fp32 y[b, t, h*64+d]
    const int b = bh >> 4, h = bh & 15;
    const float inv0 = 1.0f / li[0];
    const float inv1 = 1.0f / li[1];
    const int r  = lane >> 2;
    const int cc = 2 * (lane & 3);
    const int t0 = q0 + wid * 16 + r;
    #pragma unroll
    for (int dt = 0; dt < 8; dt++) {
        const int d = h * 64 + 8 * dt + cc;
        *(float2*)(g_Y + ((size_t)b * T_ + t0) * C_ + d) =
            make_float2(O[dt][0] * inv0, O[dt][1] * inv0);
        *(float2*)(g_Y + ((size_t)b * T_ + t0 + 8) * C_ + d) =
            make_float2(O[dt][2] * inv1, O[dt][3] * inv1);
    }
}

// ---------------------------------------------------------------------------
extern "C" void kernel_launch(void* const* d_in, const int* in_sizes, int n_in,
                              void* d_out, int out_size)
{
    const float* x  = (const float*)d_in[0];
    const float* Wq = (const float*)d_in[1];
    const float* Wk = (const float*)d_in[2];
    const float* Wv = (const float*)d_in[3];
    const float* Wo = (const float*)d_in[4];
    float* out = (float*)d_out;

    float* yp;
    cudaGetSymbolAddress((void**)&yp, g_Y);

    cudaFuncSetAttribute(proj_mma<0>, cudaFuncAttributeMaxDynamicSharedMemorySize,
                         PROJ_SMEM);
    cudaFuncSetAttribute(proj_mma<1>, cudaFuncAttributeMaxDynamicSharedMemorySize,
                         PROJ_SMEM);
    cudaFuncSetAttribute(attn_mma, cudaFuncAttributeMaxDynamicSharedMemorySize,
                         AT_SMEM);

    // fused QKV projection -> fp16 scratch
    proj_mma<0><<<dim3(24, M_/128), 256, PROJ_SMEM>>>(x, Wq, Wk, Wv, nullptr);

    // tensor-core flash attention
    attn_mma<<<dim3(T_/128, B_*H_), 256, AT_SMEM>>>();

    // output projection
    proj_mma<1><<<dim3(8, M_/128), 256, PROJ_SMEM>>>(yp, Wo, Wo, Wo, out);
}

// round 5
// speedup vs baseline: 3.8999x; 1.3243x over previous
#include <cuda_runtime.h>
#include <cuda_fp16.h>
#include <math.h>
#include <cstdint>

#define B_ 2
#define T_ 2048
#define C_ 1024
#define H_ 16
#define D_ 64
#define M_ (B_*T_)   // 4096

// Scratch (device globals -- allocation-free)
__device__ __half g_Xh[M_*C_];         // x fp16 hi
__device__ __half g_Xl[M_*C_];         // x fp16 residual
__device__ __half g_W16[4*C_*C_];      // Wq,Wk,Wv,Wo fp16
__device__ __half g_Qh[B_*H_*T_*D_];   // Q*0.125 fp16 hi
__device__ __half g_Ql[B_*H_*T_*D_];   // Q*0.125 fp16 residual
__device__ __half g_Kh[B_*H_*T_*D_];   // K fp16
__device__ __half g_Vh[B_*H_*T_*D_];   // V fp16
__device__ __half g_Yh[M_*C_];         // attn out fp16 hi
__device__ __half g_Yl[M_*C_];         // attn out fp16 residual

extern __shared__ char dynsmem[];

// ===========================================================================
// helpers
// ===========================================================================
__device__ __forceinline__ uint32_t smem_u32(const void* p) {
    uint32_t a;
    asm("{ .reg .u64 t; cvta.to.shared.u64 t, %1; cvt.u32.u64 %0, t; }"
        : "=r"(a) : "l"(p));
    return a;
}
__device__ __forceinline__ void ldm_x4(uint32_t r[4], uint32_t addr) {
    asm volatile("ldmatrix.sync.aligned.m8n8.x4.shared.b16 {%0,%1,%2,%3}, [%4];"
                 : "=r"(r[0]), "=r"(r[1]), "=r"(r[2]), "=r"(r[3]) : "r"(addr));
}
__device__ __forceinline__ void ldm_x4_t(uint32_t r[4], uint32_t addr) {
    asm volatile("ldmatrix.sync.aligned.m8n8.x4.trans.shared.b16 {%0,%1,%2,%3}, [%4];"
                 : "=r"(r[0]), "=r"(r[1]), "=r"(r[2]), "=r"(r[3]) : "r"(addr));
}
__device__ __forceinline__ void mma_fp(float c[4], const uint32_t a[4],
                                       const uint32_t b[2]) {
    asm volatile(
        "mma.sync.aligned.m16n8k16.row.col.f32.f16.f16.f32 "
        "{%0,%1,%2,%3}, {%4,%5,%6,%7}, {%8,%9}, {%0,%1,%2,%3};"
        : "+f"(c[0]), "+f"(c[1]), "+f"(c[2]), "+f"(c[3])
        : "r"(a[0]), "r"(a[1]), "r"(a[2]), "r"(a[3]), "r"(b[0]), "r"(b[1]));
}
__device__ __forceinline__ uint32_t packh(__half a, __half b) {
    return (uint32_t)__half_as_ushort(a)
         | ((uint32_t)__half_as_ushort(b) << 16);
}
__device__ __forceinline__ void psplit(float a, float b, uint32_t& hi, uint32_t& lo) {
    __half h0 = __float2half_rn(a), h1 = __float2half_rn(b);
    hi = packh(h0, h1);
    lo = packh(__float2half_rn(a - __half2float(h0)),
               __float2half_rn(b - __half2float(h1)));
}
__device__ __forceinline__ void cpa16(uint32_t dst, const void* src) {
    asm volatile("cp.async.cg.shared.global [%0], [%1], 16;" :: "r"(dst), "l"(src));
}
#define CP_COMMIT()  asm volatile("cp.async.commit_group;" ::: "memory")
#define CP_WAIT0()   asm volatile("cp.async.wait_group 0;" ::: "memory")
#define CP_WAIT1()   asm volatile("cp.async.wait_group 1;" ::: "memory")
#define CP_WAIT2()   asm volatile("cp.async.wait_group 2;" ::: "memory")

// ===========================================================================
// Preconvert: X -> fp16 hi/lo, W{q,k,v,o} -> fp16 single.
// grid (1024, 5) x 256 threads.
// ===========================================================================
__global__ void __launch_bounds__(256) preconv(
    const float* __restrict__ X,
    const float* __restrict__ Wq, const float* __restrict__ Wk,
    const float* __restrict__ Wv, const float* __restrict__ Wo)
{
    const int y = blockIdx.y;
    const int i = blockIdx.x * 256 + threadIdx.x;   // float4 index
    if (y == 0) {
        #pragma unroll
        for (int j = 0; j < 4; j++) {
            const int idx = i + j * 262144;
            const float4 v = ((const float4*)X)[idx];
            const __half h0 = __float2half_rn(v.x), h1 = __float2half_rn(v.y);
            const __half h2 = __float2half_rn(v.z), h3 = __float2half_rn(v.w);
            uint2 hi, lo;
            hi.x = packh(h0, h1); hi.y = packh(h2, h3);
            lo.x = packh(__float2half_rn(v.x - __half2float(h0)),
                         __float2half_rn(v.y - __half2float(h1)));
            lo.y = packh(__float2half_rn(v.z - __half2float(h2)),
                         __float2half_rn(v.w - __half2float(h3)));
            ((uint2*)g_Xh)[idx] = hi;
            ((uint2*)g_Xl)[idx] = lo;
        }
    } else {
        const float* W = (y == 1) ? Wq : (y == 2) ? Wk : (y == 3) ? Wv : Wo;
        const float4 v = ((const float4*)W)[i];
        uint2 h;
        h.x = packh(__float2half_rn(v.x), __float2half_rn(v.y));
        h.y = packh(__float2half_rn(v.z), __float2half_rn(v.w));
        ((uint2*)(g_W16 + (size_t)(y - 1) * C_ * C_))[i] = h;
    }
}

// ===========================================================================
// Projection GEMM, fp16 2-pass: out = (Ah + Al) @ W16^T.
// CTA tile 128x128, K-block 32, 3-stage cp.async ring, 8 warps (64x32 each).
// MODE 0: fused QKV -> fp16 scratch (Q scaled+split; K,V single fp16)
// MODE 1: fp32 [M,N] out (final projection)
// ===========================================================================
#define PJ_P       40                 // halfs per smem row (32 data + 8 pad)
#define PJ_TILE_H  (128*PJ_P)         // 5120 halfs per tile
#define PJ_STG_H   (3*PJ_TILE_H)      // Ah, Al, W tiles per stage
#define PJ_SMEM    (3*PJ_STG_H*2)     // 3 stages = 92160 B

template<int MODE>
__global__ void __launch_bounds__(256) proj2(
    const __half* __restrict__ Ahg, const __half* __restrict__ Alg,
    float* __restrict__ fout)
{
    const uint32_t sbu = smem_u32(dynsmem);
    const int tid  = threadIdx.x;
    const int wid  = tid >> 5, lane = tid & 31;
    const int wm   = wid & 1,  wn   = wid >> 1;
    const int mat  = (MODE == 0) ? (blockIdx.x >> 3) : 3;
    const int bn   = (blockIdx.x & 7) * 128;
    const int bm   = blockIdx.y * 128;
    const __half* Wg = g_W16 + (size_t)mat * C_ * C_;

    const int qd   = lane >> 3;
    const int aoff = (wm * 64 + (lane & 7) + (qd & 1) * 8) * PJ_P + (qd >> 1) * 8;
    const int boff = (wn * 32 + (lane & 7) + (qd >> 1) * 8) * PJ_P + (qd & 1) * 8;

    float acc[4][4][4] = {};
    const int NKB = C_ / 32;   // 32

    // cp.async: 1536 16B-chunks per K-block (Ah/Al/W x 128 rows x 4 chunks)
    auto prefetch = [&](int kb, int stg) {
        const uint32_t st = sbu + (uint32_t)(stg * PJ_STG_H) * 2;
        #pragma unroll
        for (int i = 0; i < 6; i++) {
            const int idx  = tid + i * 256;
            const int tile = idx >> 9;
            const int rem  = idx & 511;
            const int r    = rem >> 2;
            const int ch   = rem & 3;
            const __half* src =
                (tile == 0 ? Ahg + (size_t)(bm + r) * C_
               : tile == 1 ? Alg + (size_t)(bm + r) * C_
                           : Wg  + (size_t)(bn + r) * C_) + kb * 32 + ch * 8;
            cpa16(st + (uint32_t)(tile * PJ_TILE_H + r * PJ_P + ch * 8) * 2, src);
        }
    };

    prefetch(0, 0); CP_COMMIT();
    prefetch(1, 1); CP_COMMIT();

    for (int kb = 0; kb < NKB; kb++) {
        if (kb + 2 < NKB) prefetch(kb + 2, (kb + 2) % 3);
        CP_COMMIT();
        CP_WAIT2();
        __syncthreads();

        const uint32_t st = sbu + (uint32_t)((kb % 3) * PJ_STG_H) * 2;
        const uint32_t ah = st;
        const uint32_t al = st +     PJ_TILE_H * 2;
        const uint32_t wb = st + 2 * PJ_TILE_H * 2;
        #pragma unroll
        for (int ks = 0; ks < 2; ks++) {
            const int kso = ks * 16;
            uint32_t Af[4][4], Lf[4][4], Bf[2][4];
            #pragma unroll
            for (int mi = 0; mi < 4; mi++)
                ldm_x4(Af[mi], ah + (uint32_t)(aoff + mi*16*PJ_P + kso) * 2);
            #pragma unroll
            for (int np = 0; np < 2; np++)
                ldm_x4(Bf[np], wb + (uint32_t)(boff + np*16*PJ_P + kso) * 2);
            #pragma unroll
            for (int mi = 0; mi < 4; mi++)
                #pragma unroll
                for (int ni = 0; ni < 4; ni++)
                    mma_fp(acc[mi][ni], Af[mi], &Bf[ni>>1][(ni&1)*2]);
            #pragma unroll
            for (int mi = 0; mi < 4; mi++)
                ldm_x4(Lf[mi], al + (uint32_t)(aoff + mi*16*PJ_P + kso) * 2);
            #pragma unroll
            for (int mi = 0; mi < 4; mi++)
                #pragma unroll
                for (int ni = 0; ni < 4; ni++)
                    mma_fp(acc[mi][ni], Lf[mi], &Bf[ni>>1][(ni&1)*2]);
        }
        __syncthreads();
    }

    // epilogue
    const int g  = lane >> 2;
    const int i2 = (lane & 3) * 2;
    #pragma unroll
    for (int mi = 0; mi < 4; mi++) {
        #pragma unroll
        for (int ni = 0; ni < 4; ni++) {
            const int col = bn + wn * 32 + ni * 8 + i2;
            #pragma unroll
            for (int half = 0; half < 2; half++) {
                const int m = bm + wm * 64 + mi * 16 + g + half * 8;
                const float vx = acc[mi][ni][half*2], vy = acc[mi][ni][half*2+1];
                if (MODE == 0) {
                    const int b = m >> 11, t = m & (T_ - 1);
                    const int h = col >> 6, d = col & 63;
                    const size_t idx = (((size_t)(b*H_ + h) * T_ + t) << 6) + d;
                    if (mat == 0) {
                        uint32_t hi, lo;
                        psplit(vx * 0.125f, vy * 0.125f, hi, lo);
                        *(uint32_t*)(g_Qh + idx) = hi;
                        *(uint32_t*)(g_Ql + idx) = lo;
                    } else if (mat == 1) {
                        *(uint32_t*)(g_Kh + idx) =
                            packh(__float2half_rn(vx), __float2half_rn(vy));
                    } else {
                        *(uint32_t*)(g_Vh + idx) =
                            packh(__float2half_rn(vx), __float2half_rn(vy));
                    }
                } else {
                    *(float2*)(fout + (size_t)m * C_ + col) = make_float2(vx, vy);
                }
            }
        }
    }
}

// ===========================================================================
// Flash attention on mma.sync fp16.  BQ=128, BK=64, 8 warps (16 q-rows each).
// S = (Qh+Ql)*K ; O = (Ph+Pl)*V ; epilogue writes Yh/Yl fp16.
// ===========================================================================
#define AT_PB   144
#define AT_KV   (64*AT_PB)
#define AT_STG  (2*AT_KV)
#define AT_SMEM (2*AT_STG)

__global__ void __launch_bounds__(256) attn_mma()
{
    char* sm = dynsmem;
    const uint32_t sb = smem_u32(sm);
    const int tid  = threadIdx.x;
    const int wid  = tid >> 5, lane = tid & 31;
    const int bh   = blockIdx.y;
    const int qt   = gridDim.x - 1 - blockIdx.x;
    const int q0   = qt * 128;

    const size_t base = (size_t)bh * (T_ * D_);
    const __half* Qhg = g_Qh + base + (size_t)q0 * D_;
    const __half* Qlg = g_Ql + base + (size_t)q0 * D_;
    const __half* Kg  = g_Kh + base;
    const __half* Vg  = g_Vh + base;

    {
        #pragma unroll
        for (int i = 0; i < 8; i++) {
            const int c   = tid + i * 256;
            const int arr = c >> 10;
            const int g1  = c & 1023;
            const int r   = g1 >> 3;
            const int ch  = g1 & 7;
            const uint4 v = *(const uint4*)((arr ? Qlg : Qhg) + r * 64 + ch * 8);
            *(uint4*)(sm + arr * AT_STG + r * AT_PB + ch * 16) = v;
        }
    }
    __syncthreads();

    uint32_t qfh[4][4], qfl[4][4];
    {
        const uint32_t qb = sb + (uint32_t)((wid * 16 + (lane & 15)) * AT_PB
                                            + (lane >> 4) * 16);
        #pragma unroll
        for (int ks = 0; ks < 4; ks++) {
            ldm_x4(qfh[ks], qb + ks * 32);
            ldm_x4(qfl[ks], qb + AT_STG + ks * 32);
        }
    }
    __syncthreads();

    float S[8][4];
    float O[8][4] = {};
    float mi[2] = {-1e30f, -1e30f};
    float li[2] = {0.0f, 0.0f};

    const int nkt    = 2 * qt + 2;
    const int maskst = 2 * qt;

    auto prefetch = [&](int kt, int stg) {
        #pragma unroll
        for (int i = 0; i < 4; i++) {
            const int c   = tid + i * 256;
            const int arr = c >> 9;
            const int g1  = c & 511;
            const int r   = g1 >> 3;
            const int ch  = g1 & 7;
            const __half* src = (arr ? Vg : Kg) + (size_t)(kt * 64 + r) * 64 + ch * 8;
            cpa16(sb + stg * AT_STG + arr * AT_KV + r * AT_PB + ch * 16, src);
        }
    };

    prefetch(0, 0);
    CP_COMMIT();

    for (int kt = 0; kt < nkt; kt++) {
        const int cur = kt & 1;
        if (kt + 1 < nkt) {
            prefetch(kt + 1, cur ^ 1);
            CP_COMMIT();
            CP_WAIT1();
        } else {
            CP_WAIT0();
        }
        __syncthreads();

        const bool active = (kt * 64) <= (q0 + wid * 16 + 15);
        if (active) {
            const uint32_t kb = sb + cur * AT_STG;
            const uint32_t vb = kb + AT_KV;
            const uint32_t lm = (uint32_t)((lane & 15) * AT_PB + (lane >> 4) * 16);

            #pragma unroll
            for (int j = 0; j < 8; j++)
                #pragma unroll
                for (int e = 0; e < 4; e++) S[j][e] = 0.0f;

            #pragma unroll
            for (int ks = 0; ks < 4; ks++) {
                #pragma unroll
                for (int j16 = 0; j16 < 4; j16++) {
                    uint32_t kf[4];
                    ldm_x4(kf, kb + lm + (uint32_t)(j16 * 16 * AT_PB + ks * 32));
                    uint32_t b0[2] = {kf[0], kf[2]};
                    uint32_t b1[2] = {kf[1], kf[3]};
                    mma_fp(S[2*j16],   qfh[ks], b0);
                    mma_fp(S[2*j16],   qfl[ks], b0);
                    mma_fp(S[2*j16+1], qfh[ks], b1);
                    mma_fp(S[2*j16+1], qfl[ks], b1);
                }
            }

            if (kt >= maskst) {
                const int qr = q0 + wid * 16 + (lane >> 2);
                const int kcb = kt * 64 + 2 * (lane & 3);
                #pragma unroll
                for (int j = 0; j < 8; j++) {
                    const int kc = kcb + 8 * j;
                    if (kc     > qr)     S[j][0] = -1e30f;
                    if (kc + 1 > qr)     S[j][1] = -1e30f;
                    if (kc     > qr + 8) S[j][2] = -1e30f;
                    if (kc + 1 > qr + 8) S[j][3] = -1e30f;
                }
            }

            float m0 = -1e30f, m1 = -1e30f;
            #pragma unroll
            for (int j = 0; j < 8; j++) {
                m0 = fmaxf(m0, fmaxf(S[j][0], S[j][1]));
                m1 = fmaxf(m1, fmaxf(S[j][2], S[j][3]));
            }
            m0 = fmaxf(m0, __shfl_xor_sync(0xffffffffu, m0, 1));
            m0 = fmaxf(m0, __shfl_xor_sync(0xffffffffu, m0, 2));
            m1 = fmaxf(m1, __shfl_xor_sync(0xffffffffu, m1, 1));
            m1 = fmaxf(m1, __shfl_xor_sync(0xffffffffu, m1, 2));
            const float nm0 = fmaxf(mi[0], m0);
            const float nm1 = fmaxf(mi[1], m1);
            float s0 = 0.0f, s1 = 0.0f;
            #pragma unroll
            for (int j = 0; j < 8; j++) {
                S[j][0] = __expf(S[j][0] - nm0);
                S[j][1] = __expf(S[j][1] - nm0);
                S[j][2] = __expf(S[j][2] - nm1);
                S[j][3] = __expf(S[j][3] - nm1);
                s0 += S[j][0] + S[j][1];
                s1 += S[j][2] + S[j][3];
            }
            s0 += __shfl_xor_sync(0xffffffffu, s0, 1);
            s0 += __shfl_xor_sync(0xffffffffu, s0, 2);
            s1 += __shfl_xor_sync(0xffffffffu, s1, 1);
            s1 += __shfl_xor_sync(0xffffffffu, s1, 2);
            const float c0 = __expf(mi[0] - nm0);
            const float c1 = __expf(mi[1] - nm1);
            li[0] = li[0] * c0 + s0;  mi[0] = nm0;
            li[1] = li[1] * c1 + s1;  mi[1] = nm1;
            #pragma unroll
            for (int j = 0; j < 8; j++) {
                O[j][0] *= c0; O[j][1] *= c0;
                O[j][2] *= c1; O[j][3] *= c1;
            }

            #pragma unroll
            for (int j16 = 0; j16 < 4; j16++) {
                uint32_t ph[4], pl[4];
                psplit(S[2*j16][0],   S[2*j16][1],   ph[0], pl[0]);
                psplit(S[2*j16][2],   S[2*j16][3],   ph[1], pl[1]);
                psplit(S[2*j16+1][0], S[2*j16+1][1], ph[2], pl[2]);
                psplit(S[2*j16+1][2], S[2*j16+1][3], ph[3], pl[3]);
                #pragma unroll
                for (int dt = 0; dt < 4; dt++) {
                    uint32_t vf[4];
                    ldm_x4_t(vf, vb + lm + (uint32_t)(j16 * 16 * AT_PB + dt * 32));
                    uint32_t vb0[2] = {vf[0], vf[1]};
                    uint32_t vb1[2] = {vf[2], vf[3]};
                    mma_fp(O[2*dt],   ph, vb0);
                    mma_fp(O[2*dt],   pl, vb0);
                    mma_fp(O[2*dt+1], ph, vb1);
                    mma_fp(O[2*dt+1], pl, vb1);
                }
            }
        }
        __syncthreads();
    }

    // epilogue: normalize, write fp16 hi/lo y[b, t, h*64+d]
    const int b = bh >> 4, h = bh & 15;
    const float inv0 = 1.0f / li[0];
    const float inv1 = 1.0f / li[1];
    const int r  = lane >> 2;
    const int cc = 2 * (lane & 3);
    const int t0 = q0 + wid * 16 + r;
    #pragma unroll
    for (int dt = 0; dt < 8; dt++) {
        const int d = h * 64 + 8 * dt + cc;
        const size_t i0 = ((size_t)b * T_ + t0) * C_ + d;
        const size_t i1 = ((size_t)b * T_ + t0 + 8) * C_ + d;
        uint32_t hi, lo;
        psplit(O[dt][0] * inv0, O[dt][1] * inv0, hi, lo);
        *(uint32_t*)(g_Yh + i0) = hi;
        *(uint32_t*)(g_Yl + i0) = lo;
        psplit(O[dt][2] * inv1, O[dt][3] * inv1, hi, lo);
        *(uint32_t*)(g_Yh + i1) = hi;
        *(uint32_t*)(g_Yl + i1) = lo;
    }
}

// ---------------------------------------------------------------------------
extern "C" void kernel_launch(void* const* d_in, const int* in_sizes, int n_in,
                              void* d_out, int out_size)
{
    const float* x  = (const float*)d_in[0];
    const float* Wq = (const float*)d_in[1];
    const float* Wk = (const float*)d_in[2];
    const float* Wv = (const float*)d_in[3];
    const float* Wo = (const float*)d_in[4];
    float* out = (float*)d_out;

    __half *xh, *xl, *yh, *yl;
    cudaGetSymbolAddress((void**)&xh, g_Xh);
    cudaGetSymbolAddress((void**)&xl, g_Xl);
    cudaGetSymbolAddress((void**)&yh, g_Yh);
    cudaGetSymbolAddress((void**)&yl, g_Yl);

    cudaFuncSetAttribute(proj2<0>, cudaFuncAttributeMaxDynamicSharedMemorySize,
                         PJ_SMEM);
    cudaFuncSetAttribute(proj2<1>, cudaFuncAttributeMaxDynamicSharedMemorySize,
                         PJ_SMEM);
    cudaFuncSetAttribute(attn_mma, cudaFuncAttributeMaxDynamicSharedMemorySize,
                         AT_SMEM);

    preconv<<<dim3(1024, 5), 256>>>(x, Wq, Wk, Wv, Wo);

    // fused QKV projection -> fp16 scratch
    proj2<0><<<dim3(24, M_/128), 256, PJ_SMEM>>>(xh, xl, nullptr);

    // tensor-core flash attention
    attn_mma<<<dim3(T_/128, B_*H_), 256, AT_SMEM>>>();

    // output projection
    proj2<1><<<dim3(8, M_/128), 256, PJ_SMEM>>>(yh, yl, out);
}

// round 6
// speedup vs baseline: 4.2984x; 1.1022x over previous
#include <cuda_runtime.h>
#include <cuda_fp16.h>
#include <math.h>
#include <cstdint>

#define B_ 2
#define T_ 2048
#define C_ 1024
#define H_ 16
#define D_ 64
#define M_ (B_*T_)   // 4096

// Scratch (device globals -- allocation-free)
__device__ __half g_Xh[M_*C_];         // x fp16 hi
__device__ __half g_Xl[M_*C_];         // x fp16 residual
__device__ __half g_W16[4*C_*C_];      // Wq,Wk,Wv,Wo fp16
__device__ __half g_Qh[B_*H_*T_*D_];   // Q*0.125 fp16 hi
__device__ __half g_Ql[B_*H_*T_*D_];   // Q*0.125 fp16 residual
__device__ __half g_Kh[B_*H_*T_*D_];   // K fp16
__device__ __half g_Vh[B_*H_*T_*D_];   // V fp16
__device__ __half g_Yh[M_*C_];         // attn out fp16 hi
__device__ __half g_Yl[M_*C_];         // attn out fp16 residual

extern __shared__ char dynsmem[];

// ===========================================================================
// helpers
// ===========================================================================
__device__ __forceinline__ uint32_t smem_u32(const void* p) {
    uint32_t a;
    asm("{ .reg .u64 t; cvta.to.shared.u64 t, %1; cvt.u32.u64 %0, t; }"
        : "=r"(a) : "l"(p));
    return a;
}
__device__ __forceinline__ void ldm_x4(uint32_t r[4], uint32_t addr) {
    asm volatile("ldmatrix.sync.aligned.m8n8.x4.shared.b16 {%0,%1,%2,%3}, [%4];"
                 : "=r"(r[0]), "=r"(r[1]), "=r"(r[2]), "=r"(r[3]) : "r"(addr));
}
__device__ __forceinline__ void ldm_x4_t(uint32_t r[4], uint32_t addr) {
    asm volatile("ldmatrix.sync.aligned.m8n8.x4.trans.shared.b16 {%0,%1,%2,%3}, [%4];"
                 : "=r"(r[0]), "=r"(r[1]), "=r"(r[2]), "=r"(r[3]) : "r"(addr));
}
__device__ __forceinline__ void mma_fp(float c[4], const uint32_t a[4],
                                       const uint32_t b[2]) {
    asm volatile(
        "mma.sync.aligned.m16n8k16.row.col.f32.f16.f16.f32 "
        "{%0,%1,%2,%3}, {%4,%5,%6,%7}, {%8,%9}, {%0,%1,%2,%3};"
        : "+f"(c[0]), "+f"(c[1]), "+f"(c[2]), "+f"(c[3])
        : "r"(a[0]), "r"(a[1]), "r"(a[2]), "r"(a[3]), "r"(b[0]), "r"(b[1]));
}
__device__ __forceinline__ uint32_t packh(__half a, __half b) {
    return (uint32_t)__half_as_ushort(a)
         | ((uint32_t)__half_as_ushort(b) << 16);
}
__device__ __forceinline__ void psplit(float a, float b, uint32_t& hi, uint32_t& lo) {
    __half h0 = __float2half_rn(a), h1 = __float2half_rn(b);
    hi = packh(h0, h1);
    lo = packh(__float2half_rn(a - __half2float(h0)),
               __float2half_rn(b - __half2float(h1)));
}
__device__ __forceinline__ void cpa16(uint32_t dst, const void* src) {
    asm volatile("cp.async.cg.shared.global [%0], [%1], 16;" :: "r"(dst), "l"(src));
}
#define CP_COMMIT()  asm volatile("cp.async.commit_group;" ::: "memory")
#define CP_WAIT0()   asm volatile("cp.async.wait_group 0;" ::: "memory")
#define CP_WAIT1()   asm volatile("cp.async.wait_group 1;" ::: "memory")

// ===========================================================================
// Preconvert: X -> fp16 hi/lo, W{q,k,v,o} -> fp16 single.
// ===========================================================================
__global__ void __launch_bounds__(256) preconv(
    const float* __restrict__ X,
    const float* __restrict__ Wq, const float* __restrict__ Wk,
    const float* __restrict__ Wv, const float* __restrict__ Wo)
{
    const int y = blockIdx.y;
    const int i = blockIdx.x * 256 + threadIdx.x;   // float4 index
    if (y == 0) {
        #pragma unroll
        for (int j = 0; j < 4; j++) {
            const int idx = i + j * 262144;
            const float4 v = ((const float4*)X)[idx];
            const __half h0 = __float2half_rn(v.x), h1 = __float2half_rn(v.y);
            const __half h2 = __float2half_rn(v.z), h3 = __float2half_rn(v.w);
            uint2 hi, lo;
            hi.x = packh(h0, h1); hi.y = packh(h2, h3);
            lo.x = packh(__float2half_rn(v.x - __half2float(h0)),
                         __float2half_rn(v.y - __half2float(h1)));
            lo.y = packh(__float2half_rn(v.z - __half2float(h2)),
                         __float2half_rn(v.w - __half2float(h3)));
            ((uint2*)g_Xh)[idx] = hi;
            ((uint2*)g_Xl)[idx] = lo;
        }
    } else {
        const float* W = (y == 1) ? Wq : (y == 2) ? Wk : (y == 3) ? Wv : Wo;
        const float4 v = ((const float4*)W)[i];
        uint2 h;
        h.x = packh(__float2half_rn(v.x), __float2half_rn(v.y));
        h.y = packh(__float2half_rn(v.z), __float2half_rn(v.w));
        ((uint2*)(g_W16 + (size_t)(y - 1) * C_ * C_))[i] = h;
    }
}

// ===========================================================================
// Projection GEMM, fp16 2-pass: out = (Ah + Al) @ W16^T.
// CTA tile 128x128, K-block 64, 2-stage cp.async ring (55.3KB/stage,
// 110.6KB/CTA -> 2 CTAs/SM), 8 warps (64x32 each).
// MODE 0: fused QKV -> fp16 scratch; MODE 1: fp32 [M,N] out.
// ===========================================================================
#define PJ_P       72                 // halfs per smem row (64 data + 8 pad)
#define PJ_TILE_H  (128*PJ_P)         // 9216 halfs per tile
#define PJ_STG_H   (3*PJ_TILE_H)      // Ah, Al, W tiles per stage
#define PJ_SMEM    (2*PJ_STG_H*2)     // 2 stages = 110592 B

template<int MODE>
__global__ void __launch_bounds__(256) proj2(
    const __half* __restrict__ Ahg, const __half* __restrict__ Alg,
    float* __restrict__ fout)
{
    const uint32_t sbu = smem_u32(dynsmem);
    const int tid  = threadIdx.x;
    const int wid  = tid >> 5, lane = tid & 31;
    const int wm   = wid & 1,  wn   = wid >> 1;
    const int mat  = (MODE == 0) ? (blockIdx.x >> 3) : 3;
    const int bn   = (blockIdx.x & 7) * 128;
    const int bm   = blockIdx.y * 128;
    const __half* Wg = g_W16 + (size_t)mat * C_ * C_;

    const int qd   = lane >> 3;
    const int aoff = (wm * 64 + (lane & 7) + (qd & 1) * 8) * PJ_P + (qd >> 1) * 8;
    const int boff = (wn * 32 + (lane & 7) + (qd >> 1) * 8) * PJ_P + (qd & 1) * 8;

    float acc[4][4][4] = {};
    const int NKB = C_ / 64;   // 16

    // cp.async: 3072 16B-chunks per K-block (Ah/Al/W x 128 rows x 8 chunks)
    auto prefetch = [&](int kb, int stg) {
        const uint32_t st = sbu + (uint32_t)(stg * PJ_STG_H) * 2;
        #pragma unroll
        for (int i = 0; i < 12; i++) {
            const int idx  = tid + i * 256;
            const int tile = idx >> 10;
            const int rem  = idx & 1023;
            const int r    = rem >> 3;
            const int ch   = rem & 7;
            const __half* src =
                (tile == 0 ? Ahg + (size_t)(bm + r) * C_
               : tile == 1 ? Alg + (size_t)(bm + r) * C_
                           : Wg  + (size_t)(bn + r) * C_) + kb * 64 + ch * 8;
            cpa16(st + (uint32_t)(tile * PJ_TILE_H + r * PJ_P + ch * 8) * 2, src);
        }
    };

    prefetch(0, 0); CP_COMMIT();

    for (int kb = 0; kb < NKB; kb++) {
        if (kb + 1 < NKB) {
            prefetch(kb + 1, (kb + 1) & 1);
            CP_COMMIT();
            CP_WAIT1();
        } else {
            CP_WAIT0();
        }
        __syncthreads();

        const uint32_t st = sbu + (uint32_t)((kb & 1) * PJ_STG_H) * 2;
        const uint32_t ah = st;
        const uint32_t al = st +     PJ_TILE_H * 2;
        const uint32_t wb = st + 2 * PJ_TILE_H * 2;
        #pragma unroll
        for (int ks = 0; ks < 4; ks++) {
            const int kso = ks * 16;
            uint32_t Af[4][4], Lf[4][4], Bf[2][4];
            #pragma unroll
            for (int mi = 0; mi < 4; mi++)
                ldm_x4(Af[mi], ah + (uint32_t)(aoff + mi*16*PJ_P + kso) * 2);
            #pragma unroll
            for (int np = 0; np < 2; np++)
                ldm_x4(Bf[np], wb + (uint32_t)(boff + np*16*PJ_P + kso) * 2);
            #pragma unroll
            for (int mi = 0; mi < 4; mi++)
                #pragma unroll
                for (int ni = 0; ni < 4; ni++)
                    mma_fp(acc[mi][ni], Af[mi], &Bf[ni>>1][(ni&1)*2]);
            #pragma unroll
            for (int mi = 0; mi < 4; mi++)
                ldm_x4(Lf[mi], al + (uint32_t)(aoff + mi*16*PJ_P + kso) * 2);
            #pragma unroll
            for (int mi = 0; mi < 4; mi++)
                #pragma unroll
                for (int ni = 0; ni < 4; ni++)
                    mma_fp(acc[mi][ni], Lf[mi], &Bf[ni>>1][(ni&1)*2]);
        }
        __syncthreads();
    }

    // epilogue
    const int g  = lane >> 2;
    const int i2 = (lane & 3) * 2;
    #pragma unroll
    for (int mi = 0; mi < 4; mi++) {
        #pragma unroll
        for (int ni = 0; ni < 4; ni++) {
            const int col = bn + wn * 32 + ni * 8 + i2;
            #pragma unroll
            for (int half = 0; half < 2; half++) {
                const int m = bm + wm * 64 + mi * 16 + g + half * 8;
                const float vx = acc[mi][ni][half*2], vy = acc[mi][ni][half*2+1];
                if (MODE == 0) {
                    const int b = m >> 11, t = m & (T_ - 1);
                    const int h = col >> 6, d = col & 63;
                    const size_t idx = (((size_t)(b*H_ + h) * T_ + t) << 6) + d;
                    if (mat == 0) {
                        uint32_t hi, lo;
                        psplit(vx * 0.125f, vy * 0.125f, hi, lo);
                        *(uint32_t*)(g_Qh + idx) = hi;
                        *(uint32_t*)(g_Ql + idx) = lo;
                    } else if (mat == 1) {
                        *(uint32_t*)(g_Kh + idx) =
                            packh(__float2half_rn(vx), __float2half_rn(vy));
                    } else {
                        *(uint32_t*)(g_Vh + idx) =
                            packh(__float2half_rn(vx), __float2half_rn(vy));
                    }
                } else {
                    *(float2*)(fout + (size_t)m * C_ + col) = make_float2(vx, vy);
                }
            }
        }
    }
}

// ===========================================================================
// Flash attention on mma.sync fp16 (unchanged from R5).
// ===========================================================================
#define AT_PB   144
#define AT_KV   (64*AT_PB)
#define AT_STG  (2*AT_KV)
#define AT_SMEM (2*AT_STG)

__global__ void __launch_bounds__(256) attn_mma()
{
    char* sm = dynsmem;
    const uint32_t sb = smem_u32(sm);
    const int tid  = threadIdx.x;
    const int wid  = tid >> 5, lane = tid & 31;
    const int bh   = blockIdx.y;
    const int qt   = gridDim.x - 1 - blockIdx.x;
    const int q0   = qt * 128;

    const size_t base = (size_t)bh * (T_ * D_);
    const __half* Qhg = g_Qh + base + (size_t)q0 * D_;
    const __half* Qlg = g_Ql + base + (size_t)q0 * D_;
    const __half* Kg  = g_Kh + base;
    const __half* Vg  = g_Vh + base;

    {
        #pragma unroll
        for (int i = 0; i < 8; i++) {
            const int c   = tid + i * 256;
            const int arr = c >> 10;
            const int g1  = c & 1023;
            const int r   = g1 >> 3;
            const int ch  = g1 & 7;
            const uint4 v = *(const uint4*)((arr ? Qlg : Qhg) + r * 64 + ch * 8);
            *(uint4*)(sm + arr * AT_STG + r * AT_PB + ch * 16) = v;
        }
    }
    __syncthreads();

    uint32_t qfh[4][4], qfl[4][4];
    {
        const uint32_t qb = sb + (uint32_t)((wid * 16 + (lane & 15)) * AT_PB
                                            + (lane >> 4) * 16);
        #pragma unroll
        for (int ks = 0; ks < 4; ks++) {
            ldm_x4(qfh[ks], qb + ks * 32);
            ldm_x4(qfl[ks], qb + AT_STG + ks * 32);
        }
    }
    __syncthreads();

    float S[8][4];
    float O[8][4] = {};
    float mi[2] = {-1e30f, -1e30f};
    float li[2] = {0.0f, 0.0f};

    const int nkt    = 2 * qt + 2;
    const int maskst = 2 * qt;

    auto prefetch = [&](int kt, int stg) {
        #pragma unroll
        for (int i = 0; i < 4; i++) {
            const int c   = tid + i * 256;
            const int arr = c >> 9;
            const int g1  = c & 511;
            const int r   = g1 >> 3;
            const int ch  = g1 & 7;
            const __half* src = (arr ? Vg : Kg) + (size_t)(kt * 64 + r) * 64 + ch * 8;
            cpa16(sb + stg * AT_STG + arr * AT_KV + r * AT_PB + ch * 16, src);
        }
    };

    prefetch(0, 0);
    CP_COMMIT();

    for (int kt = 0; kt < nkt; kt++) {
        const int cur = kt & 1;
        if (kt + 1 < nkt) {
            prefetch(kt + 1, cur ^ 1);
            CP_COMMIT();
            CP_WAIT1();
        } else {
            CP_WAIT0();
        }
        __syncthreads();

        const bool active = (kt * 64) <= (q0 + wid * 16 + 15);
        if (active) {
            const uint32_t kb = sb + cur * AT_STG;
            const uint32_t vb = kb + AT_KV;
            const uint32_t lm = (uint32_t)((lane & 15) * AT_PB + (lane >> 4) * 16);

            #pragma unroll
            for (int j = 0; j < 8; j++)
                #pragma unroll
                for (int e = 0; e < 4; e++) S[j][e] = 0.0f;

            #pragma unroll
            for (int ks = 0; ks < 4; ks++) {
                #pragma unroll
                for (int j16 = 0; j16 < 4; j16++) {
                    uint32_t kf[4];
                    ldm_x4(kf, kb + lm + (uint32_t)(j16 * 16 * AT_PB + ks * 32));
                    uint32_t b0[2] = {kf[0], kf[2]};
                    uint32_t b1[2] = {kf[1], kf[3]};
                    mma_fp(S[2*j16],   qfh[ks], b0);
                    mma_fp(S[2*j16],   qfl[ks], b0);
                    mma_fp(S[2*j16+1], qfh[ks], b1);
                    mma_fp(S[2*j16+1], qfl[ks], b1);
                }
            }

            if (kt >= maskst) {
                const int qr = q0 + wid * 16 + (lane >> 2);
                const int kcb = kt * 64 + 2 * (lane & 3);
                #pragma unroll
                for (int j = 0; j < 8; j++) {
                    const int kc = kcb + 8 * j;
                    if (kc     > qr)     S[j][0] = -1e30f;
                    if (kc + 1 > qr)     S[j][1] = -1e30f;
                    if (kc     > qr + 8) S[j][2] = -1e30f;
                    if (kc + 1 > qr + 8) S[j][3] = -1e30f;
                }
            }

            float m0 = -1e30f, m1 = -1e30f;
            #pragma unroll
            for (int j = 0; j < 8; j++) {
                m0 = fmaxf(m0, fmaxf(S[j][0], S[j][1]));
                m1 = fmaxf(m1, fmaxf(S[j][2], S[j][3]));
            }
            m0 = fmaxf(m0, __shfl_xor_sync(0xffffffffu, m0, 1));
            m0 = fmaxf(m0, __shfl_xor_sync(0xffffffffu, m0, 2));
            m1 = fmaxf(m1, __shfl_xor_sync(0xffffffffu, m1, 1));
            m1 = fmaxf(m1, __shfl_xor_sync(0xffffffffu, m1, 2));
            const float nm0 = fmaxf(mi[0], m0);
            const float nm1 = fmaxf(mi[1], m1);
            float s0 = 0.0f, s1 = 0.0f;
            #pragma unroll
            for (int j = 0; j < 8; j++) {
                S[j][0] = __expf(S[j][0] - nm0);
                S[j][1] = __expf(S[j][1] - nm0);
                S[j][2] = __expf(S[j][2] - nm1);
                S[j][3] = __expf(S[j][3] - nm1);
                s0 += S[j][0] + S[j][1];
                s1 += S[j][2] + S[j][3];
            }
            s0 += __shfl_xor_sync(0xffffffffu, s0, 1);
            s0 += __shfl_xor_sync(0xffffffffu, s0, 2);
            s1 += __shfl_xor_sync(0xffffffffu, s1, 1);
            s1 += __shfl_xor_sync(0xffffffffu, s1, 2);
            const float c0 = __expf(mi[0] - nm0);
            const float c1 = __expf(mi[1] - nm1);
            li[0] = li[0] * c0 + s0;  mi[0] = nm0;
            li[1] = li[1] * c1 + s1;  mi[1] = nm1;
            #pragma unroll
            for (int j = 0; j < 8; j++) {
                O[j][0] *= c0; O[j][1] *= c0;
                O[j][2] *= c1; O[j][3] *= c1;
            }

            #pragma unroll
            for (int j16 = 0; j16 < 4; j16++) {
                uint32_t ph[4], pl[4];
                psplit(S[2*j16][0],   S[2*j16][1],   ph[0], pl[0]);
                psplit(S[2*j16][2],   S[2*j16][3],   ph[1], pl[1]);
                psplit(S[2*j16+1][0], S[2*j16+1][1], ph[2], pl[2]);
                psplit(S[2*j16+1][2], S[2*j16+1][3], ph[3], pl[3]);
                #pragma unroll
                for (int dt = 0; dt < 4; dt++) {
                    uint32_t vf[4];
                    ldm_x4_t(vf, vb + lm + (uint32_t)(j16 * 16 * AT_PB + dt * 32));
                    uint32_t vb0[2] = {vf[0], vf[1]};
                    uint32_t vb1[2] = {vf[2], vf[3]};
                    mma_fp(O[2*dt],   ph, vb0);
                    mma_fp(O[2*dt],   pl, vb0);
                    mma_fp(O[2*dt+1], ph, vb1);
                    mma_fp(O[2*dt+1], pl, vb1);
                }
            }
        }
        __syncthreads();
    }

    // epilogue: normalize, write fp16 hi/lo y[b, t, h*64+d]
    const int b = bh >> 4, h = bh & 15;
    const float inv0 = 1.0f / li[0];
    const float inv1 = 1.0f / li[1];
    const int r  = lane >> 2;
    const int cc = 2 * (lane & 3);
    const int t0 = q0 + wid * 16 + r;
    #pragma unroll
    for (int dt = 0; dt < 8; dt++) {
        const int d = h * 64 + 8 * dt + cc;
        const size_t i0 = ((size_t)b * T_ + t0) * C_ + d;
        const size_t i1 = ((size_t)b * T_ + t0 + 8) * C_ + d;
        uint32_t hi, lo;
        psplit(O[dt][0] * inv0, O[dt][1] * inv0, hi, lo);
        *(uint32_t*)(g_Yh + i0) = hi;
        *(uint32_t*)(g_Yl + i0) = lo;
        psplit(O[dt][2] * inv1, O[dt][3] * inv1, hi, lo);
        *(uint32_t*)(g_Yh + i1) = hi;
        *(uint32_t*)(g_Yl + i1) = lo;
    }
}

// ---------------------------------------------------------------------------
extern "C" void kernel_launch(void* const* d_in, const int* in_sizes, int n_in,
                              void* d_out, int out_size)
{
    const float* x  = (const float*)d_in[0];
    const float* Wq = (const float*)d_in[1];
    const float* Wk = (const float*)d_in[2];
    const float* Wv = (const float*)d_in[3];
    const float* Wo = (const float*)d_in[4];
    float* out = (float*)d_out;

    __half *xh, *xl, *yh, *yl;
    cudaGetSymbolAddress((void**)&xh, g_Xh);
    cudaGetSymbolAddress((void**)&xl, g_Xl);
    cudaGetSymbolAddress((void**)&yh, g_Yh);
    cudaGetSymbolAddress((void**)&yl, g_Yl);

    cudaFuncSetAttribute(proj2<0>, cudaFuncAttributeMaxDynamicSharedMemorySize,
                         PJ_SMEM);
    cudaFuncSetAttribute(proj2<1>, cudaFuncAttributeMaxDynamicSharedMemorySize,
                         PJ_SMEM);
    cudaFuncSetAttribute(attn_mma, cudaFuncAttributeMaxDynamicSharedMemorySize,
                         AT_SMEM);

    preconv<<<dim3(1024, 5), 256>>>(x, Wq, Wk, Wv, Wo);

    // fused QKV projection -> fp16 scratch
    proj2<0><<<dim3(24, M_/128), 256, PJ_SMEM>>>(xh, xl, nullptr);

    // tensor-core flash attention
    attn_mma<<<dim3(T_/128, B_*H_), 256, AT_SMEM>>>();

    // output projection
    proj2<1><<<dim3(8, M_/128), 256, PJ_SMEM>>>(yh, yl, out);
}

// round 7
// speedup vs baseline: 5.0163x; 1.1670x over previous
#include <cuda_runtime.h>
#include <cuda_fp16.h>
#include <math.h>
#include <cstdint>

#define B_ 2
#define T_ 2048
#define C_ 1024
#define H_ 16
#define D_ 64
#define M_ (B_*T_)   // 4096

// Scratch (device globals -- allocation-free)
__device__ __half g_Xh[M_*C_];         // x fp16 hi
__device__ __half g_W16[4*C_*C_];      // Wq,Wk,Wv,Wo fp16
__device__ __half g_Qh[B_*H_*T_*D_];   // Q*0.125 fp16 hi
__device__ __half g_Ql[B_*H_*T_*D_];   // Q*0.125 fp16 residual
__device__ __half g_Kh[B_*H_*T_*D_];   // K fp16
__device__ __half g_Vh[B_*H_*T_*D_];   // V fp16
__device__ __half g_Yh[M_*C_];         // attn out fp16 hi
__device__ __half g_Yl[M_*C_];         // attn out fp16 residual

extern __shared__ char dynsmem[];

// ===========================================================================
// helpers
// ===========================================================================
__device__ __forceinline__ uint32_t smem_u32(const void* p) {
    uint32_t a;
    asm("{ .reg .u64 t; cvta.to.shared.u64 t, %1; cvt.u32.u64 %0, t; }"
        : "=r"(a) : "l"(p));
    return a;
}
__device__ __forceinline__ void ldm_x4(uint32_t r[4], uint32_t addr) {
    asm volatile("ldmatrix.sync.aligned.m8n8.x4.shared.b16 {%0,%1,%2,%3}, [%4];"
                 : "=r"(r[0]), "=r"(r[1]), "=r"(r[2]), "=r"(r[3]) : "r"(addr));
}
__device__ __forceinline__ void ldm_x4_t(uint32_t r[4], uint32_t addr) {
    asm volatile("ldmatrix.sync.aligned.m8n8.x4.trans.shared.b16 {%0,%1,%2,%3}, [%4];"
                 : "=r"(r[0]), "=r"(r[1]), "=r"(r[2]), "=r"(r[3]) : "r"(addr));
}
__device__ __forceinline__ void mma_fp(float c[4], const uint32_t a[4],
                                       const uint32_t b[2]) {
    asm volatile(
        "mma.sync.aligned.m16n8k16.row.col.f32.f16.f16.f32 "
        "{%0,%1,%2,%3}, {%4,%5,%6,%7}, {%8,%9}, {%0,%1,%2,%3};"
        : "+f"(c[0]), "+f"(c[1]), "+f"(c[2]), "+f"(c[3])
        : "r"(a[0]), "r"(a[1]), "r"(a[2]), "r"(a[3]), "r"(b[0]), "r"(b[1]));
}
__device__ __forceinline__ uint32_t packh(__half a, __half b) {
    return (uint32_t)__half_as_ushort(a)
         | ((uint32_t)__half_as_ushort(b) << 16);
}
__device__ __forceinline__ void psplit(float a, float b, uint32_t& hi, uint32_t& lo) {
    __half h0 = __float2half_rn(a), h1 = __float2half_rn(b);
    hi = packh(h0, h1);
    lo = packh(__float2half_rn(a - __half2float(h0)),
               __float2half_rn(b - __half2float(h1)));
}
__device__ __forceinline__ void cpa16(uint32_t dst, const void* src) {
    asm volatile("cp.async.cg.shared.global [%0], [%1], 16;" :: "r"(dst), "l"(src));
}
#define CP_COMMIT()  asm volatile("cp.async.commit_group;" ::: "memory")
#define CP_WAIT0()   asm volatile("cp.async.wait_group 0;" ::: "memory")
#define CP_WAIT1()   asm volatile("cp.async.wait_group 1;" ::: "memory")

// ===========================================================================
// Preconvert: X -> fp16 hi, W{q,k,v,o} -> fp16 single.
// ===========================================================================
__global__ void __launch_bounds__(256) preconv(
    const float* __restrict__ X,
    const float* __restrict__ Wq, const float* __restrict__ Wk,
    const float* __restrict__ Wv, const float* __restrict__ Wo)
{
    const int y = blockIdx.y;
    const int i = blockIdx.x * 256 + threadIdx.x;   // float4 index
    if (y == 0) {
        #pragma unroll
        for (int j = 0; j < 4; j++) {
            const int idx = i + j * 262144;
            const float4 v = ((const float4*)X)[idx];
            uint2 hi;
            hi.x = packh(__float2half_rn(v.x), __float2half_rn(v.y));
            hi.y = packh(__float2half_rn(v.z), __float2half_rn(v.w));
            ((uint2*)g_Xh)[idx] = hi;
        }
    } else {
        const float* W = (y == 1) ? Wq : (y == 2) ? Wk : (y == 3) ? Wv : Wo;
        const float4 v = ((const float4*)W)[i];
        uint2 h;
        h.x = packh(__float2half_rn(v.x), __float2half_rn(v.y));
        h.y = packh(__float2half_rn(v.z), __float2half_rn(v.w));
        ((uint2*)(g_W16 + (size_t)(y - 1) * C_ * C_))[i] = h;
    }
}

// ===========================================================================
// Projection GEMM, fp16: out = (Ah [+ Al]) @ W16^T.
// CTA tile 128x128, K-block 64, 2-stage cp.async ring, 8 warps (64x32 each).
// NP = number of A passes (1 or 2).
// MODE 0 (NP=1): fused QKV -> fp16 scratch; stage 2 tiles, 73.7KB -> 3 CTA/SM
// MODE 1 (NP=2): fp32 [M,N] out; stage 3 tiles, 110.6KB -> 2 CTA/SM
// ===========================================================================
#define PJ_P       72                 // halfs per smem row (64 data + 8 pad)
#define PJ_TILE_H  (128*PJ_P)         // 9216 halfs per tile

template<int MODE, int NP>
__global__ void __launch_bounds__(256) proj2(
    const __half* __restrict__ Ahg, const __half* __restrict__ Alg,
    float* __restrict__ fout)
{
    constexpr int NT    = NP + 1;              // tiles per stage (A[,Al],W)
    constexpr int STG_H = NT * PJ_TILE_H;

    const uint32_t sbu = smem_u32(dynsmem);
    const int tid  = threadIdx.x;
    const int wid  = tid >> 5, lane = tid & 31;
    const int wm   = wid & 1,  wn   = wid >> 1;
    const int mat  = (MODE == 0) ? (blockIdx.x >> 3) : 3;
    const int bn   = (blockIdx.x & 7) * 128;
    const int bm   = blockIdx.y * 128;
    const __half* Wg = g_W16 + (size_t)mat * C_ * C_;

    const int qd   = lane >> 3;
    const int aoff = (wm * 64 + (lane & 7) + (qd & 1) * 8) * PJ_P + (qd >> 1) * 8;
    const int boff = (wn * 32 + (lane & 7) + (qd >> 1) * 8) * PJ_P + (qd & 1) * 8;

    float acc[4][4][4] = {};
    const int NKB = C_ / 64;   // 16

    auto prefetch = [&](int kb, int stg) {
        const uint32_t st = sbu + (uint32_t)(stg * STG_H) * 2;
        #pragma unroll
        for (int i = 0; i < NT * 4; i++) {
            const int idx  = tid + i * 256;
            const int tile = idx >> 10;            // 0..NT-1
            const int rem  = idx & 1023;
            const int r    = rem >> 3;
            const int ch   = rem & 7;
            const __half* src =
                (tile == 0            ? Ahg + (size_t)(bm + r) * C_
               : (NP == 2 && tile == 1) ? Alg + (size_t)(bm + r) * C_
                                        : Wg  + (size_t)(bn + r) * C_) + kb * 64 + ch * 8;
            cpa16(st + (uint32_t)(tile * PJ_TILE_H + r * PJ_P + ch * 8) * 2, src);
        }
    };

    prefetch(0, 0); CP_COMMIT();

    for (int kb = 0; kb < NKB; kb++) {
        if (kb + 1 < NKB) {
            prefetch(kb + 1, (kb + 1) & 1);
            CP_COMMIT();
            CP_WAIT1();
        } else {
            CP_WAIT0();
        }
        __syncthreads();

        const uint32_t st = sbu + (uint32_t)((kb & 1) * STG_H) * 2;
        const uint32_t ah = st;
        const uint32_t al = st +            PJ_TILE_H * 2;
        const uint32_t wb = st + (NT - 1) * PJ_TILE_H * 2;
        #pragma unroll
        for (int ks = 0; ks < 4; ks++) {
            const int kso = ks * 16;
            uint32_t Af[4][4], Bf[2][4];
            #pragma unroll
            for (int mi = 0; mi < 4; mi++)
                ldm_x4(Af[mi], ah + (uint32_t)(aoff + mi*16*PJ_P + kso) * 2);
            #pragma unroll
            for (int np = 0; np < 2; np++)
                ldm_x4(Bf[np], wb + (uint32_t)(boff + np*16*PJ_P + kso) * 2);
            #pragma unroll
            for (int mi = 0; mi < 4; mi++)
                #pragma unroll
                for (int ni = 0; ni < 4; ni++)
                    mma_fp(acc[mi][ni], Af[mi], &Bf[ni>>1][(ni&1)*2]);
            if (NP == 2) {
                uint32_t Lf[4][4];
                #pragma unroll
                for (int mi = 0; mi < 4; mi++)
                    ldm_x4(Lf[mi], al + (uint32_t)(aoff + mi*16*PJ_P + kso) * 2);
                #pragma unroll
                for (int mi = 0; mi < 4; mi++)
                    #pragma unroll
                    for (int ni = 0; ni < 4; ni++)
                        mma_fp(acc[mi][ni], Lf[mi], &Bf[ni>>1][(ni&1)*2]);
            }
        }
        __syncthreads();
    }

    // epilogue
    const int g  = lane >> 2;
    const int i2 = (lane & 3) * 2;
    #pragma unroll
    for (int mi = 0; mi < 4; mi++) {
        #pragma unroll
        for (int ni = 0; ni < 4; ni++) {
            const int col = bn + wn * 32 + ni * 8 + i2;
            #pragma unroll
            for (int half = 0; half < 2; half++) {
                const int m = bm + wm * 64 + mi * 16 + g + half * 8;
                const float vx = acc[mi][ni][half*2], vy = acc[mi][ni][half*2+1];
                if (MODE == 0) {
                    const int b = m >> 11, t = m & (T_ - 1);
                    const int h = col >> 6, d = col & 63;
                    const size_t idx = (((size_t)(b*H_ + h) * T_ + t) << 6) + d;
                    if (mat == 0) {
                        uint32_t hi, lo;
                        psplit(vx * 0.125f, vy * 0.125f, hi, lo);
                        *(uint32_t*)(g_Qh + idx) = hi;
                        *(uint32_t*)(g_Ql + idx) = lo;
                    } else if (mat == 1) {
                        *(uint32_t*)(g_Kh + idx) =
                            packh(__float2half_rn(vx), __float2half_rn(vy));
                    } else {
                        *(uint32_t*)(g_Vh + idx) =
                            packh(__float2half_rn(vx), __float2half_rn(vy));
                    }
                } else {
                    *(float2*)(fout + (size_t)m * C_ + col) = make_float2(vx, vy);
                }
            }
        }
    }
}

#define PJ_SMEM_QKV (2*2*PJ_TILE_H*2)   // 73728 B
#define PJ_SMEM_WO  (2*3*PJ_TILE_H*2)   // 110592 B

// ===========================================================================
// Flash attention on mma.sync fp16 (unchanged from R5/R6).
// ===========================================================================
#define AT_PB   144
#define AT_KV   (64*AT_PB)
#define AT_STG  (2*AT_KV)
#define AT_SMEM (2*AT_STG)

__global__ void __launch_bounds__(256) attn_mma()
{
    char* sm = dynsmem;
    const uint32_t sb = smem_u32(sm);
    const int tid  = threadIdx.x;
    const int wid  = tid >> 5, lane = tid & 31;
    const int bh   = blockIdx.y;
    const int qt   = gridDim.x - 1 - blockIdx.x;
    const int q0   = qt * 128;

    const size_t base = (size_t)bh * (T_ * D_);
    const __half* Qhg = g_Qh + base + (size_t)q0 * D_;
    const __half* Qlg = g_Ql + base + (size_t)q0 * D_;
    const __half* Kg  = g_Kh + base;
    const __half* Vg  = g_Vh + base;

    {
        #pragma unroll
        for (int i = 0; i < 8; i++) {
            const int c   = tid + i * 256;
            const int arr = c >> 10;
            const int g1  = c & 1023;
            const int r   = g1 >> 3;
            const int ch  = g1 & 7;
            const uint4 v = *(const uint4*)((arr ? Qlg : Qhg) + r * 64 + ch * 8);
            *(uint4*)(sm + arr * AT_STG + r * AT_PB + ch * 16) = v;
        }
    }
    __syncthreads();

    uint32_t qfh[4][4], qfl[4][4];
    {
        const uint32_t qb = sb + (uint32_t)((wid * 16 + (lane & 15)) * AT_PB
                                            + (lane >> 4) * 16);
        #pragma unroll
        for (int ks = 0; ks < 4; ks++) {
            ldm_x4(qfh[ks], qb + ks * 32);
            ldm_x4(qfl[ks], qb + AT_STG + ks * 32);
        }
    }
    __syncthreads();

    float S[8][4];
    float O[8][4] = {};
    float mi[2] = {-1e30f, -1e30f};
    float li[2] = {0.0f, 0.0f};

    const int nkt    = 2 * qt + 2;
    const int maskst = 2 * qt;

    auto prefetch = [&](int kt, int stg) {
        #pragma unroll
        for (int i = 0; i < 4; i++) {
            const int c   = tid + i * 256;
            const int arr = c >> 9;
            const int g1  = c & 511;
            const int r   = g1 >> 3;
            const int ch  = g1 & 7;
            const __half* src = (arr ? Vg : Kg) + (size_t)(kt * 64 + r) * 64 + ch * 8;
            cpa16(sb + stg * AT_STG + arr * AT_KV + r * AT_PB + ch * 16, src);
        }
    };

    prefetch(0, 0);
    CP_COMMIT();

    for (int kt = 0; kt < nkt; kt++) {
        const int cur = kt & 1;
        if (kt + 1 < nkt) {
            prefetch(kt + 1, cur ^ 1);
            CP_COMMIT();
            CP_WAIT1();
        } else {
            CP_WAIT0();
        }
        __syncthreads();

        const bool active = (kt * 64) <= (q0 + wid * 16 + 15);
        if (active) {
            const uint32_t kb = sb + cur * AT_STG;
            const uint32_t vb = kb + AT_KV;
            const uint32_t lm = (uint32_t)((lane & 15) * AT_PB + (lane >> 4) * 16);

            #pragma unroll
            for (int j = 0; j < 8; j++)
                #pragma unroll
                for (int e = 0; e < 4; e++) S[j][e] = 0.0f;

            #pragma unroll
            for (int ks = 0; ks < 4; ks++) {
                #pragma unroll
                for (int j16 = 0; j16 < 4; j16++) {
                    uint32_t kf[4];
                    ldm_x4(kf, kb + lm + (uint32_t)(j16 * 16 * AT_PB + ks * 32));
                    uint32_t b0[2] = {kf[0], kf[2]};
                    uint32_t b1[2] = {kf[1], kf[3]};
                    mma_fp(S[2*j16],   qfh[ks], b0);
                    mma_fp(S[2*j16],   qfl[ks], b0);
                    mma_fp(S[2*j16+1], qfh[ks], b1);
                    mma_fp(S[2*j16+1], qfl[ks], b1);
                }
            }

            if (kt >= maskst) {
                const int qr = q0 + wid * 16 + (lane >> 2);
                const int kcb = kt * 64 + 2 * (lane & 3);
                #pragma unroll
                for (int j = 0; j < 8; j++) {
                    const int kc = kcb + 8 * j;
                    if (kc     > qr)     S[j][0] = -1e30f;
                    if (kc + 1 > qr)     S[j][1] = -1e30f;
                    if (kc     > qr + 8) S[j][2] = -1e30f;
                    if (kc + 1 > qr + 8) S[j][3] = -1e30f;
                }
            }

            float m0 = -1e30f, m1 = -1e30f;
            #pragma unroll
            for (int j = 0; j < 8; j++) {
                m0 = fmaxf(m0, fmaxf(S[j][0], S[j][1]));
                m1 = fmaxf(m1, fmaxf(S[j][2], S[j][3]));
            }
            m0 = fmaxf(m0, __shfl_xor_sync(0xffffffffu, m0, 1));
            m0 = fmaxf(m0, __shfl_xor_sync(0xffffffffu, m0, 2));
            m1 = fmaxf(m1, __shfl_xor_sync(0xffffffffu, m1, 1));
            m1 = fmaxf(m1, __shfl_xor_sync(0xffffffffu, m1, 2));
            const float nm0 = fmaxf(mi[0], m0);
            const float nm1 = fmaxf(mi[1], m1);
            float s0 = 0.0f, s1 = 0.0f;
            #pragma unroll
            for (int j = 0; j < 8; j++) {
                S[j][0] = __expf(S[j][0] - nm0);
                S[j][1] = __expf(S[j][1] - nm0);
                S[j][2] = __expf(S[j][2] - nm1);
                S[j][3] = __expf(S[j][3] - nm1);
                s0 += S[j][0] + S[j][1];
                s1 += S[j][2] + S[j][3];
            }
            s0 += __shfl_xor_sync(0xffffffffu, s0, 1);
            s0 += __shfl_xor_sync(0xffffffffu, s0, 2);
            s1 += __shfl_xor_sync(0xffffffffu, s1, 1);
            s1 += __shfl_xor_sync(0xffffffffu, s1, 2);
            const float c0 = __expf(mi[0] - nm0);
            const float c1 = __expf(mi[1] - nm1);
            li[0] = li[0] * c0 + s0;  mi[0] = nm0;
            li[1] = li[1] * c1 + s1;  mi[1] = nm1;
            #pragma unroll
            for (int j = 0; j < 8; j++) {
                O[j][0] *= c0; O[j][1] *= c0;
                O[j][2] *= c1; O[j][3] *= c1;
            }

            #pragma unroll
            for (int j16 = 0; j16 < 4; j16++) {
                uint32_t ph[4], pl[4];
                psplit(S[2*j16][0],   S[2*j16][1],   ph[0], pl[0]);
                psplit(S[2*j16][2],   S[2*j16][3],   ph[1], pl[1]);
                psplit(S[2*j16+1][0], S[2*j16+1][1], ph[2], pl[2]);
                psplit(S[2*j16+1][2], S[2*j16+1][3], ph[3], pl[3]);
                #pragma unroll
                for (int dt = 0; dt < 4; dt++) {
                    uint32_t vf[4];
                    ldm_x4_t(vf, vb + lm + (uint32_t)(j16 * 16 * AT_PB + dt * 32));
                    uint32_t vb0[2] = {vf[0], vf[1]};
                    uint32_t vb1[2] = {vf[2], vf[3]};
                    mma_fp(O[2*dt],   ph, vb0);
                    mma_fp(O[2*dt],   pl, vb0);
                    mma_fp(O[2*dt+1], ph, vb1);
                    mma_fp(O[2*dt+1], pl, vb1);
                }
            }
        }
        __syncthreads();
    }

    // epilogue: normalize, write fp16 hi/lo y[b, t, h*64+d]
    const int b = bh >> 4, h = bh & 15;
    const float inv0 = 1.0f / li[0];
    const float inv1 = 1.0f / li[1];
    const int r  = lane >> 2;
    const int cc = 2 * (lane & 3);
    const int t0 = q0 + wid * 16 + r;
    #pragma unroll
    for (int dt = 0; dt < 8; dt++) {
        const int d = h * 64 + 8 * dt + cc;
        const size_t i0 = ((size_t)b * T_ + t0) * C_ + d;
        const size_t i1 = ((size_t)b * T_ + t0 + 8) * C_ + d;
        uint32_t hi, lo;
        psplit(O[dt][0] * inv0, O[dt][1] * inv0, hi, lo);
        *(uint32_t*)(g_Yh + i0) = hi;
        *(uint32_t*)(g_Yl + i0) = lo;
        psplit(O[dt][2] * inv1, O[dt][3] * inv1, hi, lo);
        *(uint32_t*)(g_Yh + i1) = hi;
        *(uint32_t*)(g_Yl + i1) = lo;
    }
}

// ---------------------------------------------------------------------------
extern "C" void kernel_launch(void* const* d_in, const int* in_sizes, int n_in,
                              void* d_out, int out_size)
{
    const float* x  = (const float*)d_in[0];
    const float* Wq = (const float*)d_in[1];
    const float* Wk = (const float*)d_in[2];
    const float* Wv = (const float*)d_in[3];
    const float* Wo = (const float*)d_in[4];
    float* out = (float*)d_out;

    __half *xh, *yh, *yl;
    cudaGetSymbolAddress((void**)&xh, g_Xh);
    cudaGetSymbolAddress((void**)&yh, g_Yh);
    cudaGetSymbolAddress((void**)&yl, g_Yl);

    cudaFuncSetAttribute(proj2<0,1>, cudaFuncAttributeMaxDynamicSharedMemorySize,
                         PJ_SMEM_QKV);
    cudaFuncSetAttribute(proj2<1,2>, cudaFuncAttributeMaxDynamicSharedMemorySize,
                         PJ_SMEM_WO);
    cudaFuncSetAttribute(attn_mma, cudaFuncAttributeMaxDynamicSharedMemorySize,
                         AT_SMEM);

    preconv<<<dim3(1024, 5), 256>>>(x, Wq, Wk, Wv, Wo);

    // fused QKV projection (single-pass A) -> fp16 scratch
    proj2<0,1><<<dim3(24, M_/128), 256, PJ_SMEM_QKV>>>(xh, nullptr, nullptr);

    // tensor-core flash attention
    attn_mma<<<dim3(T_/128, B_*H_), 256, AT_SMEM>>>();

    // output projection (2-pass Yh+Yl for accuracy)
    proj2<1,2><<<dim3(8, M_/128), 256, PJ_SMEM_WO>>>(yh, yl, out);
}

// round 11
// speedup vs baseline: 6.2477x; 1.2455x over previous
#include <cuda_runtime.h>
#include <cuda_fp16.h>
#include <math.h>
#include <cstdint>

#define B_ 2
#define T_ 2048
#define C_ 1024
#define H_ 16
#define D_ 64
#define M_ (B_*T_)   // 4096

// Scratch (device globals -- allocation-free)
__device__ __half g_Xh[M_*C_];         // x fp16
__device__ __half g_W16[4*C_*C_];      // Wq,Wk,Wv,Wo fp16
__device__ __half g_Qh[B_*H_*T_*D_];   // Q*0.125 fp16
__device__ __half g_Kh[B_*H_*T_*D_];   // K fp16
__device__ __half g_Vh[B_*H_*T_*D_];   // V fp16
__device__ __half g_Yh[M_*C_];         // attn out fp16 hi
__device__ __half g_Yl[M_*C_];         // attn out fp16 residual

extern __shared__ char dynsmem[];

// ===========================================================================
// helpers
// ===========================================================================
__device__ __forceinline__ uint32_t smem_u32(const void* p) {
    uint32_t a;
    asm("{ .reg .u64 t; cvta.to.shared.u64 t, %1; cvt.u32.u64 %0, t; }"
        : "=r"(a) : "l"(p));
    return a;
}
__device__ __forceinline__ void ldm_x4(uint32_t r[4], uint32_t addr) {
    asm volatile("ldmatrix.sync.aligned.m8n8.x4.shared.b16 {%0,%1,%2,%3}, [%4];"
                 : "=r"(r[0]), "=r"(r[1]), "=r"(r[2]), "=r"(r[3]) : "r"(addr));
}
__device__ __forceinline__ void ldm_x4_t(uint32_t r[4], uint32_t addr) {
    asm volatile("ldmatrix.sync.aligned.m8n8.x4.trans.shared.b16 {%0,%1,%2,%3}, [%4];"
                 : "=r"(r[0]), "=r"(r[1]), "=r"(r[2]), "=r"(r[3]) : "r"(addr));
}
__device__ __forceinline__ void mma_fp(float c[4], const uint32_t a[4],
                                       const uint32_t b[2]) {
    asm volatile(
        "mma.sync.aligned.m16n8k16.row.col.f32.f16.f16.f32 "
        "{%0,%1,%2,%3}, {%4,%5,%6,%7}, {%8,%9}, {%0,%1,%2,%3};"
        : "+f"(c[0]), "+f"(c[1]), "+f"(c[2]), "+f"(c[3])
        : "r"(a[0]), "r"(a[1]), "r"(a[2]), "r"(a[3]), "r"(b[0]), "r"(b[1]));
}
__device__ __forceinline__ uint32_t packh(__half a, __half b) {
    return (uint32_t)__half_as_ushort(a)
         | ((uint32_t)__half_as_ushort(b) << 16);
}
__device__ __forceinline__ uint32_t packf(float a, float b) {
    return packh(__float2half_rn(a), __float2half_rn(b));
}
__device__ __forceinline__ void psplit(float a, float b, uint32_t& hi, uint32_t& lo) {
    __half h0 = __float2half_rn(a), h1 = __float2half_rn(b);
    hi = packh(h0, h1);
    lo = packh(__float2half_rn(a - __half2float(h0)),
               __float2half_rn(b - __half2float(h1)));
}
__device__ __forceinline__ void cpa16(uint32_t dst, const void* src) {
    asm volatile("cp.async.cg.shared.global [%0], [%1], 16;" :: "r"(dst), "l"(src));
}
#define CP_COMMIT()  asm volatile("cp.async.commit_group;" ::: "memory")
#define CP_WAIT0()   asm volatile("cp.async.wait_group 0;" ::: "memory")
#define CP_WAIT1()   asm volatile("cp.async.wait_group 1;" ::: "memory")

// ===========================================================================
// Preconvert: X -> fp16, W{q,k,v,o} -> fp16.
// ===========================================================================
__global__ void __launch_bounds__(256) preconv(
    const float* __restrict__ X,
    const float* __restrict__ Wq, const float* __restrict__ Wk,
    const float* __restrict__ Wv, const float* __restrict__ Wo)
{
    const int y = blockIdx.y;
    const int i = blockIdx.x * 256 + threadIdx.x;   // float4 index
    if (y == 0) {
        #pragma unroll
        for (int j = 0; j < 4; j++) {
            const int idx = i + j * 262144;
            const float4 v = ((const float4*)X)[idx];
            uint2 hi;
            hi.x = packf(v.x, v.y);
            hi.y = packf(v.z, v.w);
            ((uint2*)g_Xh)[idx] = hi;
        }
    } else {
        const float* W = (y == 1) ? Wq : (y == 2) ? Wk : (y == 3) ? Wv : Wo;
        const float4 v = ((const float4*)W)[i];
        uint2 h;
        h.x = packf(v.x, v.y);
        h.y = packf(v.z, v.w);
        ((uint2*)(g_W16 + (size_t)(y - 1) * C_ * C_))[i] = h;
    }
}

// ===========================================================================
// Projection GEMM, fp16: out = (Ah [+ Al]) @ W16^T.
// CTA tile 128x128, K-block 64, 2-stage cp.async ring, 8 warps (64x32 each).
// MODE 0 (NP=1): fused QKV -> fp16 scratch; 73.7KB -> 3 CTA/SM
// MODE 1 (NP=2): fp32 [M,N] out; 110.6KB -> 2 CTA/SM
// ===========================================================================
#define PJ_P       72                 // halfs per smem row (64 data + 8 pad)
#define PJ_TILE_H  (128*PJ_P)         // 9216 halfs per tile

template<int MODE, int NP>
__global__ void __launch_bounds__(256) proj2(
    const __half* __restrict__ Ahg, const __half* __restrict__ Alg,
    float* __restrict__ fout)
{
    constexpr int NT    = NP + 1;              // tiles per stage (A[,Al],W)
    constexpr int STG_H = NT * PJ_TILE_H;

    const uint32_t sbu = smem_u32(dynsmem);
    const int tid  = threadIdx.x;
    const int wid  = tid >> 5, lane = tid & 31;
    const int wm   = wid & 1,  wn   = wid >> 1;
    const int mat  = (MODE == 0) ? (blockIdx.x >> 3) : 3;
    const int bn   = (blockIdx.x & 7) * 128;
    const int bm   = blockIdx.y * 128;
    const __half* Wg = g_W16 + (size_t)mat * C_ * C_;

    const int qd   = lane >> 3;
    const int aoff = (wm * 64 + (lane & 7) + (qd & 1) * 8) * PJ_P + (qd >> 1) * 8;
    const int boff = (wn * 32 + (lane & 7) + (qd >> 1) * 8) * PJ_P + (qd & 1) * 8;

    float acc[4][4][4] = {};
    const int NKB = C_ / 64;   // 16

    auto prefetch = [&](int kb, int stg) {
        const uint32_t st = sbu + (uint32_t)(stg * STG_H) * 2;
        #pragma unroll
        for (int i = 0; i < NT * 4; i++) {
            const int idx  = tid + i * 256;
            const int tile = idx >> 10;            // 0..NT-1
            const int rem  = idx & 1023;
            const int r    = rem >> 3;
            const int ch   = rem & 7;
            const __half* src =
                (tile == 0            ? Ahg + (size_t)(bm + r) * C_
               : (NP == 2 && tile == 1) ? Alg + (size_t)(bm + r) * C_
                                        : Wg  + (size_t)(bn + r) * C_) + kb * 64 + ch * 8;
            cpa16(st + (uint32_t)(tile * PJ_TILE_H + r * PJ_P + ch * 8) * 2, src);
        }
    };

    prefetch(0, 0); CP_COMMIT();

    for (int kb = 0; kb < NKB; kb++) {
        if (kb + 1 < NKB) {
            prefetch(kb + 1, (kb + 1) & 1);
            CP_COMMIT();
            CP_WAIT1();
        } else {
            CP_WAIT0();
        }
        __syncthreads();

        const uint32_t st = sbu + (uint32_t)((kb & 1) * STG_H) * 2;
        const uint32_t ah = st;
        const uint32_t al = st +            PJ_TILE_H * 2;
        const uint32_t wb = st + (NT - 1) * PJ_TILE_H * 2;
        #pragma unroll
        for (int ks = 0; ks < 4; ks++) {
            const int kso = ks * 16;
            uint32_t Af[4][4], Bf[2][4];
            #pragma unroll
            for (int mi = 0; mi < 4; mi++)
                ldm_x4(Af[mi], ah + (uint32_t)(aoff + mi*16*PJ_P + kso) * 2);
            #pragma unroll
            for (int np = 0; np < 2; np++)
                ldm_x4(Bf[np], wb + (uint32_t)(boff + np*16*PJ_P + kso) * 2);
            #pragma unroll
            for (int mi = 0; mi < 4; mi++)
                #pragma unroll
                for (int ni = 0; ni < 4; ni++)
                    mma_fp(acc[mi][ni], Af[mi], &Bf[ni>>1][(ni&1)*2]);
            if (NP == 2) {
                uint32_t Lf[4][4];
                #pragma unroll
                for (int mi = 0; mi < 4; mi++)
                    ldm_x4(Lf[mi], al + (uint32_t)(aoff + mi*16*PJ_P + kso) * 2);
                #pragma unroll
                for (int mi = 0; mi < 4; mi++)
                    #pragma unroll
                    for (int ni = 0; ni < 4; ni++)
                        mma_fp(acc[mi][ni], Lf[mi], &Bf[ni>>1][(ni&1)*2]);
            }
        }
        __syncthreads();
    }

    // epilogue
    const int g  = lane >> 2;
    const int i2 = (lane & 3) * 2;
    #pragma unroll
    for (int mi = 0; mi < 4; mi++) {
        #pragma unroll
        for (int ni = 0; ni < 4; ni++) {
            const int col = bn + wn * 32 + ni * 8 + i2;
            #pragma unroll
            for (int half = 0; half < 2; half++) {
                const int m = bm + wm * 64 + mi * 16 + g + half * 8;
                const float vx = acc[mi][ni][half*2], vy = acc[mi][ni][half*2+1];
                if (MODE == 0) {
                    const int b = m >> 11, t = m & (T_ - 1);
                    const int h = col >> 6, d = col & 63;
                    const size_t idx = (((size_t)(b*H_ + h) * T_ + t) << 6) + d;
                    if (mat == 0) {
                        *(uint32_t*)(g_Qh + idx) = packf(vx * 0.125f, vy * 0.125f);
                    } else if (mat == 1) {
                        *(uint32_t*)(g_Kh + idx) = packf(vx, vy);
                    } else {
                        *(uint32_t*)(g_Vh + idx) = packf(vx, vy);
                    }
                } else {
                    *(float2*)(fout + (size_t)m * C_ + col) = make_float2(vx, vy);
                }
            }
        }
    }
}

#define PJ_SMEM_QKV (2*2*PJ_TILE_H*2)   // 73728 B
#define PJ_SMEM_WO  (2*3*PJ_TILE_H*2)   // 110592 B

// ===========================================================================
// Flash attention on mma.sync fp16, single-pass Q and P.
// BQ=128, BK=64, 8 warps (16 q-rows each).
// ===========================================================================
#define AT_PB   144
#define AT_KV   (64*AT_PB)
#define AT_STG  (2*AT_KV)
#define AT_SMEM (2*AT_STG)

__global__ void __launch_bounds__(256) attn_mma()
{
    char* sm = dynsmem;
    const uint32_t sb = smem_u32(sm);
    const int tid  = threadIdx.x;
    const int wid  = tid >> 5, lane = tid & 31;
    const int bh   = blockIdx.y;
    const int qt   = gridDim.x - 1 - blockIdx.x;
    const int q0   = qt * 128;

    const size_t base = (size_t)bh * (T_ * D_);
    const __half* Qg = g_Qh + base + (size_t)q0 * D_;
    const __half* Kg = g_Kh + base;
    const __half* Vg = g_Vh + base;

    // stage Q (128 rows x 64 halfs) into smem
    {
        #pragma unroll
        for (int i = 0; i < 4; i++) {
            const int c  = tid + i * 256;     // 0..1023
            const int r  = c >> 3;
            const int ch = c & 7;
            const uint4 v = *(const uint4*)(Qg + r * 64 + ch * 8);
            *(uint4*)(sm + r * AT_PB + ch * 16) = v;
        }
    }
    __syncthreads();

    uint32_t qf[4][4];
    {
        const uint32_t qb = sb + (uint32_t)((wid * 16 + (lane & 15)) * AT_PB
                                            + (lane >> 4) * 16);
        #pragma unroll
        for (int ks = 0; ks < 4; ks++)
            ldm_x4(qf[ks], qb + ks * 32);
    }
    __syncthreads();

    float S[8][4];
    float O[8][4] = {};
    float mi[2] = {-1e30f, -1e30f};
    float li[2] = {0.0f, 0.0f};

    const int nkt    = 2 * qt + 2;
    const int maskst = 2 * qt;

    auto prefetch = [&](int kt, int stg) {
        #pragma unroll
        for (int i = 0; i < 4; i++) {
            const int c   = tid + i * 256;
            const int arr = c >> 9;
            const int g1  = c & 511;
            const int r   = g1 >> 3;
            const int ch  = g1 & 7;
            const __half* src = (arr ? Vg : Kg) + (size_t)(kt * 64 + r) * 64 + ch * 8;
            cpa16(sb + stg * AT_STG + arr * AT_KV + r * AT_PB + ch * 16, src);
        }
    };

    prefetch(0, 0);
    CP_COMMIT();

    for (int kt = 0; kt < nkt; kt++) {
        const int cur = kt & 1;
        if (kt + 1 < nkt) {
            prefetch(kt + 1, cur ^ 1);
            CP_COMMIT();
            CP_WAIT1();
        } else {
            CP_WAIT0();
        }
        __syncthreads();

        const bool active = (kt * 64) <= (q0 + wid * 16 + 15);
        if (active) {
            const uint32_t kb = sb + cur * AT_STG;
            const uint32_t vb = kb + AT_KV;
            const uint32_t lm = (uint32_t)((lane & 15) * AT_PB + (lane >> 4) * 16);

            #pragma unroll
            for (int j = 0; j < 8; j++)
                #pragma unroll
                for (int e = 0; e < 4; e++) S[j][e] = 0.0f;

            // ---- S = Q K^T  (single pass)
            #pragma unroll
            for (int ks = 0; ks < 4; ks++) {
                #pragma unroll
                for (int j16 = 0; j16 < 4; j16++) {
                    uint32_t kf[4];
                    ldm_x4(kf, kb + lm + (uint32_t)(j16 * 16 * AT_PB + ks * 32));
                    uint32_t b0[2] = {kf[0], kf[2]};
                    uint32_t b1[2] = {kf[1], kf[3]};
                    mma_fp(S[2*j16],   qf[ks], b0);
                    mma_fp(S[2*j16+1], qf[ks], b1);
                }
            }

            if (kt >= maskst) {
                const int qr = q0 + wid * 16 + (lane >> 2);
                const int kcb = kt * 64 + 2 * (lane & 3);
                #pragma unroll
                for (int j = 0; j < 8; j++) {
                    const int kc = kcb + 8 * j;
                    if (kc     > qr)     S[j][0] = -1e30f;
                    if (kc + 1 > qr)     S[j][1] = -1e30f;
                    if (kc     > qr + 8) S[j][2] = -1e30f;
                    if (kc + 1 > qr + 8) S[j][3] = -1e30f;
                }
            }

            float m0 = -1e30f, m1 = -1e30f;
            #pragma unroll
            for (int j = 0; j < 8; j++) {
                m0 = fmaxf(m0, fmaxf(S[j][0], S[j][1]));
                m1 = fmaxf(m1, fmaxf(S[j][2], S[j][3]));
            }
            m0 = fmaxf(m0, __shfl_xor_sync(0xffffffffu, m0, 1));
            m0 = fmaxf(m0, __shfl_xor_sync(0xffffffffu, m0, 2));
            m1 = fmaxf(m1, __shfl_xor_sync(0xffffffffu, m1, 1));
            m1 = fmaxf(m1, __shfl_xor_sync(0xffffffffu, m1, 2));
            const float nm0 = fmaxf(mi[0], m0);
            const float nm1 = fmaxf(mi[1], m1);
            float s0 = 0.0f, s1 = 0.0f;
            #pragma unroll
            for (int j = 0; j < 8; j++) {
                S[j][0] = __expf(S[j][0] - nm0);
                S[j][1] = __expf(S[j][1] - nm0);
                S[j][2] = __expf(S[j][2] - nm1);
                S[j][3] = __expf(S[j][3] - nm1);
                s0 += S[j][0] + S[j][1];
                s1 += S[j][2] + S[j][3];
            }
            s0 += __shfl_xor_sync(0xffffffffu, s0, 1);
            s0 += __shfl_xor_sync(0xffffffffu, s0, 2);
            s1 += __shfl_xor_sync(0xffffffffu, s1, 1);
            s1 += __shfl_xor_sync(0xffffffffu, s1, 2);
            const float c0 = __expf(mi[0] - nm0);
            const float c1 = __expf(mi[1] - nm1);
            li[0] = li[0] * c0 + s0;  mi[0] = nm0;
            li[1] = li[1] * c1 + s1;  mi[1] = nm1;
            #pragma unroll
            for (int j = 0; j < 8; j++) {
                O[j][0] *= c0; O[j][1] *= c0;
                O[j][2] *= c1; O[j][3] *= c1;
            }

            // ---- O += P V  (single pass)
            #pragma unroll
            for (int j16 = 0; j16 < 4; j16++) {
                uint32_t ph[4];
                ph[0] = packf(S[2*j16][0],   S[2*j16][1]);
                ph[1] = packf(S[2*j16][2],   S[2*j16][3]);
                ph[2] = packf(S[2*j16+1][0], S[2*j16+1][1]);
                ph[3] = packf(S[2*j16+1][2], S[2*j16+1][3]);
                #pragma unroll
                for (int dt = 0; dt < 4; dt++) {
                    uint32_t vf[4];
                    ldm_x4_t(vf, vb + lm + (uint32_t)(j16 * 16 * AT_PB + dt * 32));
                    uint32_t vb0[2] = {vf[0], vf[1]};
                    uint32_t vb1[2] = {vf[2], vf[3]};
                    mma_fp(O[2*dt],   ph, vb0);
                    mma_fp(O[2*dt+1], ph, vb1);
                }
            }
        }
        __syncthreads();
    }

    // epilogue: normalize, write fp16 hi/lo y[b, t, h*64+d]
    const int b = bh >> 4, h = bh & 15;
    const float inv0 = 1.0f / li[0];
    const float inv1 = 1.0f / li[1];
    const int r  = lane >> 2;
    const int cc = 2 * (lane & 3);
    const int t0 = q0 + wid * 16 + r;
    #pragma unroll
    for (int dt = 0; dt < 8; dt++) {
        const int d = h * 64 + 8 * dt + cc;
        const size_t i0 = ((size_t)b * T_ + t0) * C_ + d;
        const size_t i1 = ((size_t)b * T_ + t0 + 8) * C_ + d;
        uint32_t hi, lo;
        psplit(O[dt][0] * inv0, O[dt][1] * inv0, hi, lo);
        *(uint32_t*)(g_Yh + i0) = hi;
        *(uint32_t*)(g_Yl + i0) = lo;
        psplit(O[dt][2] * inv1, O[dt][3] * inv1, hi, lo);
        *(uint32_t*)(g_Yh + i1) = hi;
        *(uint32_t*)(g_Yl + i1) = lo;
    }
}

// ---------------------------------------------------------------------------
extern "C" void kernel_launch(void* const* d_in, const int* in_sizes, int n_in,
                              void* d_out, int out_size)
{
    const float* x  = (const float*)d_in[0];
    const float* Wq = (const float*)d_in[1];
    const float* Wk = (const float*)d_in[2];
    const float* Wv = (const float*)d_in[3];
    const float* Wo = (const float*)d_in[4];
    float* out = (float*)d_out;

    __half *xh, *yh, *yl;
    cudaGetSymbolAddress((void**)&xh, g_Xh);
    cudaGetSymbolAddress((void**)&yh, g_Yh);
    cudaGetSymbolAddress((void**)&yl, g_Yl);

    cudaFuncSetAttribute(proj2<0,1>, cudaFuncAttributeMaxDynamicSharedMemorySize,
                         PJ_SMEM_QKV);
    cudaFuncSetAttribute(proj2<1,2>, cudaFuncAttributeMaxDynamicSharedMemorySize,
                         PJ_SMEM_WO);
    cudaFuncSetAttribute(attn_mma, cudaFuncAttributeMaxDynamicSharedMemorySize,
                         AT_SMEM);

    preconv<<<dim3(1024, 5), 256>>>(x, Wq, Wk, Wv, Wo);

    // fused QKV projection (single-pass A) -> fp16 scratch
    proj2<0,1><<<dim3(24, M_/128), 256, PJ_SMEM_QKV>>>(xh, nullptr, nullptr);

    // tensor-core flash attention (single-pass Q and P)
    attn_mma<<<dim3(T_/128, B_*H_), 256, AT_SMEM>>>();

    // output projection (2-pass Yh+Yl for accuracy)
    proj2<1,2><<<dim3(8, M_/128), 256, PJ_SMEM_WO>>>(yh, yl, out);
}

// round 12
// speedup vs baseline: 6.9046x; 1.1051x over previous
#include <cuda_runtime.h>
#include <cuda_fp16.h>
#include <math.h>
#include <cstdint>

#define B_ 2
#define T_ 2048
#define C_ 1024
#define H_ 16
#define D_ 64
#define M_ (B_*T_)   // 4096

// Scratch (device globals -- allocation-free)
__device__ __half g_Xh[M_*C_];         // x fp16
__device__ __half g_W16[4*C_*C_];      // Wq,Wk,Wv,Wo fp16
__device__ __half g_Qh[B_*H_*T_*D_];   // Q*0.125 fp16
__device__ __half g_Kh[B_*H_*T_*D_];   // K fp16
__device__ __half g_Vh[B_*H_*T_*D_];   // V fp16
__device__ __half g_Yh[M_*C_];         // attn out fp16

extern __shared__ char dynsmem[];

// ===========================================================================
// helpers
// ===========================================================================
__device__ __forceinline__ uint32_t smem_u32(const void* p) {
    uint32_t a;
    asm("{ .reg .u64 t; cvta.to.shared.u64 t, %1; cvt.u32.u64 %0, t; }"
        : "=r"(a) : "l"(p));
    return a;
}
__device__ __forceinline__ void ldm_x4(uint32_t r[4], uint32_t addr) {
    asm volatile("ldmatrix.sync.aligned.m8n8.x4.shared.b16 {%0,%1,%2,%3}, [%4];"
                 : "=r"(r[0]), "=r"(r[1]), "=r"(r[2]), "=r"(r[3]) : "r"(addr));
}
__device__ __forceinline__ void ldm_x4_t(uint32_t r[4], uint32_t addr) {
    asm volatile("ldmatrix.sync.aligned.m8n8.x4.trans.shared.b16 {%0,%1,%2,%3}, [%4];"
                 : "=r"(r[0]), "=r"(r[1]), "=r"(r[2]), "=r"(r[3]) : "r"(addr));
}
__device__ __forceinline__ void mma_fp(float c[4], const uint32_t a[4],
                                       const uint32_t b[2]) {
    asm volatile(
        "mma.sync.aligned.m16n8k16.row.col.f32.f16.f16.f32 "
        "{%0,%1,%2,%3}, {%4,%5,%6,%7}, {%8,%9}, {%0,%1,%2,%3};"
        : "+f"(c[0]), "+f"(c[1]), "+f"(c[2]), "+f"(c[3])
        : "r"(a[0]), "r"(a[1]), "r"(a[2]), "r"(a[3]), "r"(b[0]), "r"(b[1]));
}
__device__ __forceinline__ uint32_t packh(__half a, __half b) {
    return (uint32_t)__half_as_ushort(a)
         | ((uint32_t)__half_as_ushort(b) << 16);
}
__device__ __forceinline__ uint32_t packf(float a, float b) {
    return packh(__float2half_rn(a), __float2half_rn(b));
}
__device__ __forceinline__ void cpa16(uint32_t dst, const void* src) {
    asm volatile("cp.async.cg.shared.global [%0], [%1], 16;" :: "r"(dst), "l"(src));
}
#define CP_COMMIT()  asm volatile("cp.async.commit_group;" ::: "memory")
#define CP_WAIT0()   asm volatile("cp.async.wait_group 0;" ::: "memory")
#define CP_WAIT1()   asm volatile("cp.async.wait_group 1;" ::: "memory")

// ===========================================================================
// Preconvert: X -> fp16, W{q,k,v,o} -> fp16.
// ===========================================================================
__global__ void __launch_bounds__(256) preconv(
    const float* __restrict__ X,
    const float* __restrict__ Wq, const float* __restrict__ Wk,
    const float* __restrict__ Wv, const float* __restrict__ Wo)
{
    const int y = blockIdx.y;
    const int i = blockIdx.x * 256 + threadIdx.x;   // float4 index
    if (y == 0) {
        #pragma unroll
        for (int j = 0; j < 4; j++) {
            const int idx = i + j * 262144;
            const float4 v = ((const float4*)X)[idx];
            uint2 hi;
            hi.x = packf(v.x, v.y);
            hi.y = packf(v.z, v.w);
            ((uint2*)g_Xh)[idx] = hi;
        }
    } else {
        const float* W = (y == 1) ? Wq : (y == 2) ? Wk : (y == 3) ? Wv : Wo;
        const float4 v = ((const float4*)W)[i];
        uint2 h;
        h.x = packf(v.x, v.y);
        h.y = packf(v.z, v.w);
        ((uint2*)(g_W16 + (size_t)(y - 1) * C_ * C_))[i] = h;
    }
}

// ===========================================================================
// Projection GEMM, fp16 single-pass: out = A16 @ W16^T.
// CTA tile 128x128, K-block 64, 2-stage cp.async ring, 8 warps (64x32 each).
// MODE 0: fused QKV -> fp16 scratch; MODE 1: fp32 [M,N] out (Wo).
// ===========================================================================
#define PJ_P       72                 // halfs per smem row (64 data + 8 pad)
#define PJ_TILE_H  (128*PJ_P)         // 9216 halfs per tile
#define PJ_SMEM    (2*2*PJ_TILE_H*2)  // 2 stages x (A,W) = 73728 B

template<int MODE>
__global__ void __launch_bounds__(256) proj2(
    const __half* __restrict__ Ahg, float* __restrict__ fout)
{
    constexpr int STG_H = 2 * PJ_TILE_H;

    const uint32_t sbu = smem_u32(dynsmem);
    const int tid  = threadIdx.x;
    const int wid  = tid >> 5, lane = tid & 31;
    const int wm   = wid & 1,  wn   = wid >> 1;
    const int mat  = (MODE == 0) ? (blockIdx.x >> 3) : 3;
    const int bn   = (blockIdx.x & 7) * 128;
    const int bm   = blockIdx.y * 128;
    const __half* Wg = g_W16 + (size_t)mat * C_ * C_;

    const int qd   = lane >> 3;
    const int aoff = (wm * 64 + (lane & 7) + (qd & 1) * 8) * PJ_P + (qd >> 1) * 8;
    const int boff = (wn * 32 + (lane & 7) + (qd >> 1) * 8) * PJ_P + (qd & 1) * 8;

    float acc[4][4][4] = {};
    const int NKB = C_ / 64;   // 16

    auto prefetch = [&](int kb, int stg) {
        const uint32_t st = sbu + (uint32_t)(stg * STG_H) * 2;
        #pragma unroll
        for (int i = 0; i < 8; i++) {
            const int idx  = tid + i * 256;
            const int tile = idx >> 10;            // 0=A, 1=W
            const int rem  = idx & 1023;
            const int r    = rem >> 3;
            const int ch   = rem & 7;
            const __half* src =
                (tile == 0 ? Ahg + (size_t)(bm + r) * C_
                           : Wg  + (size_t)(bn + r) * C_) + kb * 64 + ch * 8;
            cpa16(st + (uint32_t)(tile * PJ_TILE_H + r * PJ_P + ch * 8) * 2, src);
        }
    };

    prefetch(0, 0); CP_COMMIT();

    for (int kb = 0; kb < NKB; kb++) {
        if (kb + 1 < NKB) {
            prefetch(kb + 1, (kb + 1) & 1);
            CP_COMMIT();
            CP_WAIT1();
        } else {
            CP_WAIT0();
        }
        __syncthreads();

        const uint32_t st = sbu + (uint32_t)((kb & 1) * STG_H) * 2;
        const uint32_t ah = st;
        const uint32_t wb = st + PJ_TILE_H * 2;
        #pragma unroll
        for (int ks = 0; ks < 4; ks++) {
            const int kso = ks * 16;
            uint32_t Af[4][4], Bf[2][4];
            #pragma unroll
            for (int mi = 0; mi < 4; mi++)
                ldm_x4(Af[mi], ah + (uint32_t)(aoff + mi*16*PJ_P + kso) * 2);
            #pragma unroll
            for (int np = 0; np < 2; np++)
                ldm_x4(Bf[np], wb + (uint32_t)(boff + np*16*PJ_P + kso) * 2);
            #pragma unroll
            for (int mi = 0; mi < 4; mi++)
                #pragma unroll
                for (int ni = 0; ni < 4; ni++)
                    mma_fp(acc[mi][ni], Af[mi], &Bf[ni>>1][(ni&1)*2]);
        }
        __syncthreads();
    }

    // epilogue
    const int g  = lane >> 2;
    const int i2 = (lane & 3) * 2;
    #pragma unroll
    for (int mi = 0; mi < 4; mi++) {
        #pragma unroll
        for (int ni = 0; ni < 4; ni++) {
            const int col = bn + wn * 32 + ni * 8 + i2;
            #pragma unroll
            for (int half = 0; half < 2; half++) {
                const int m = bm + wm * 64 + mi * 16 + g + half * 8;
                const float vx = acc[mi][ni][half*2], vy = acc[mi][ni][half*2+1];
                if (MODE == 0) {
                    const int b = m >> 11, t = m & (T_ - 1);
                    const int h = col >> 6, d = col & 63;
                    const size_t idx = (((size_t)(b*H_ + h) * T_ + t) << 6) + d;
                    if (mat == 0) {
                        *(uint32_t*)(g_Qh + idx) = packf(vx * 0.125f, vy * 0.125f);
                    } else if (mat == 1) {
                        *(uint32_t*)(g_Kh + idx) = packf(vx, vy);
                    } else {
                        *(uint32_t*)(g_Vh + idx) = packf(vx, vy);
                    }
                } else {
                    *(float2*)(fout + (size_t)m * C_ + col) = make_float2(vx, vy);
                }
            }
        }
    }
}

// ===========================================================================
// Flash attention on mma.sync fp16, single-pass Q and P.
// BQ=128, 8 warps (16 q-rows each).  K/V staged in 128-row groups
// (2 x BK=64 compute sub-tiles per group) -> half the barriers/waits.
// ===========================================================================
#define AT_PB   144                   // bytes per smem row
#define AT_K128 (128*AT_PB)           // 128-row K (or V) block = 18432 B
#define AT_STG  (2*AT_K128)           // K128 + V128 per stage = 36864 B
#define AT_SMEM (2*AT_STG)            // 73728 B

__global__ void __launch_bounds__(256) attn_mma()
{
    char* sm = dynsmem;
    const uint32_t sb = smem_u32(sm);
    const int tid  = threadIdx.x;
    const int wid  = tid >> 5, lane = tid & 31;
    const int bh   = blockIdx.y;
    const int qt   = gridDim.x - 1 - blockIdx.x;    // heavy-first
    const int q0   = qt * 128;

    const size_t base = (size_t)bh * (T_ * D_);
    const __half* Qg = g_Qh + base + (size_t)q0 * D_;
    const __half* Kg = g_Kh + base;
    const __half* Vg = g_Vh + base;

    // stage Q (128 rows x 64 halfs) into smem (stage-0 area, consumed to regs)
    {
        #pragma unroll
        for (int i = 0; i < 4; i++) {
            const int c  = tid + i * 256;     // 0..1023
            const int r  = c >> 3;
            const int ch = c & 7;
            const uint4 v = *(const uint4*)(Qg + r * 64 + ch * 8);
            *(uint4*)(sm + r * AT_PB + ch * 16) = v;
        }
    }
    __syncthreads();

    uint32_t qf[4][4];
    {
        const uint32_t qb = sb + (uint32_t)((wid * 16 + (lane & 15)) * AT_PB
                                            + (lane >> 4) * 16);
        #pragma unroll
        for (int ks = 0; ks < 4; ks++)
            ldm_x4(qf[ks], qb + ks * 32);
    }
    __syncthreads();

    float S[8][4];
    float O[8][4] = {};
    float mi[2] = {-1e30f, -1e30f};
    float li[2] = {0.0f, 0.0f};

    const int ngrp = qt + 1;        // 128-row kv groups
    const int qrow0 = q0 + wid * 16 + (lane >> 2);

    // prefetch one 128-row K + V group
    auto prefetch = [&](int g, int stg) {
        #pragma unroll
        for (int i = 0; i < 8; i++) {
            const int c   = tid + i * 256;     // 0..2047
            const int arr = c >> 10;           // 0=K, 1=V
            const int g1  = c & 1023;
            const int r   = g1 >> 3;           // 0..127
            const int ch  = g1 & 7;
            const __half* src = (arr ? Vg : Kg) + (size_t)(g * 128 + r) * 64 + ch * 8;
            cpa16(sb + stg * AT_STG + arr * AT_K128 + r * AT_PB + ch * 16, src);
        }
    };

    prefetch(0, 0);
    CP_COMMIT();

    for (int g = 0; g < ngrp; g++) {
        if (g + 1 < ngrp) {
            prefetch(g + 1, (g + 1) & 1);
            CP_COMMIT();
            CP_WAIT1();
        } else {
            CP_WAIT0();
        }
        __syncthreads();

        const uint32_t stg = sb + (g & 1) * AT_STG;
        const uint32_t lm  = (uint32_t)((lane & 15) * AT_PB + (lane >> 4) * 16);

        #pragma unroll
        for (int hh = 0; hh < 2; hh++) {
            const int kt = 2 * g + hh;
            if ((kt * 64) > (q0 + wid * 16 + 15)) continue;   // fully masked

            const uint32_t kb = stg + (uint32_t)(hh * 64 * AT_PB);
            const uint32_t vb = stg + AT_K128 + (uint32_t)(hh * 64 * AT_PB);

            #pragma unroll
            for (int j = 0; j < 8; j++)
                #pragma unroll
                for (int e = 0; e < 4; e++) S[j][e] = 0.0f;

            // ---- S = Q K^T
            #pragma unroll
            for (int ks = 0; ks < 4; ks++) {
                #pragma unroll
                for (int j16 = 0; j16 < 4; j16++) {
                    uint32_t kf[4];
                    ldm_x4(kf, kb + lm + (uint32_t)(j16 * 16 * AT_PB + ks * 32));
                    uint32_t b0[2] = {kf[0], kf[2]};
                    uint32_t b1[2] = {kf[1], kf[3]};
                    mma_fp(S[2*j16],   qf[ks], b0);
                    mma_fp(S[2*j16+1], qf[ks], b1);
                }
            }

            // ---- causal mask (only the last group)
            if (kt >= 2 * qt) {
                const int kcb = kt * 64 + 2 * (lane & 3);
                #pragma unroll
                for (int j = 0; j < 8; j++) {
                    const int kc = kcb + 8 * j;
                    if (kc     > qrow0)     S[j][0] = -1e30f;
                    if (kc + 1 > qrow0)     S[j][1] = -1e30f;
                    if (kc     > qrow0 + 8) S[j][2] = -1e30f;
                    if (kc + 1 > qrow0 + 8) S[j][3] = -1e30f;
                }
            }

            // ---- online softmax (2 rows per thread)
            float m0 = -1e30f, m1 = -1e30f;
            #pragma unroll
            for (int j = 0; j < 8; j++) {
                m0 = fmaxf(m0, fmaxf(S[j][0], S[j][1]));
                m1 = fmaxf(m1, fmaxf(S[j][2], S[j][3]));
            }
            m0 = fmaxf(m0, __shfl_xor_sync(0xffffffffu, m0, 1));
            m0 = fmaxf(m0, __shfl_xor_sync(0xffffffffu, m0, 2));
            m1 = fmaxf(m1, __shfl_xor_sync(0xffffffffu, m1, 1));
            m1 = fmaxf(m1, __shfl_xor_sync(0xffffffffu, m1, 2));
            const float nm0 = fmaxf(mi[0], m0);
            const float nm1 = fmaxf(mi[1], m1);
            float s0 = 0.0f, s1 = 0.0f;
            #pragma unroll
            for (int j = 0; j < 8; j++) {
                S[j][0] = __expf(S[j][0] - nm0);
                S[j][1] = __expf(S[j][1] - nm0);
                S[j][2] = __expf(S[j][2] - nm1);
                S[j][3] = __expf(S[j][3] - nm1);
                s0 += S[j][0] + S[j][1];
                s1 += S[j][2] + S[j][3];
            }
            s0 += __shfl_xor_sync(0xffffffffu, s0, 1);
            s0 += __shfl_xor_sync(0xffffffffu, s0, 2);
            s1 += __shfl_xor_sync(0xffffffffu, s1, 1);
            s1 += __shfl_xor_sync(0xffffffffu, s1, 2);
            const float c0 = __expf(mi[0] - nm0);
            const float c1 = __expf(mi[1] - nm1);
            li[0] = li[0] * c0 + s0;  mi[0] = nm0;
            li[1] = li[1] * c1 + s1;  mi[1] = nm1;
            #pragma unroll
            for (int j = 0; j < 8; j++) {
                O[j][0] *= c0; O[j][1] *= c0;
                O[j][2] *= c1; O[j][3] *= c1;
            }

            // ---- O += P V
            #pragma unroll
            for (int j16 = 0; j16 < 4; j16++) {
                uint32_t ph[4];
                ph[0] = packf(S[2*j16][0],   S[2*j16][1]);
                ph[1] = packf(S[2*j16][2],   S[2*j16][3]);
                ph[2] = packf(S[2*j16+1][0], S[2*j16+1][1]);
                ph[3] = packf(S[2*j16+1][2], S[2*j16+1][3]);
                #pragma unroll
                for (int dt = 0; dt < 4; dt++) {
                    uint32_t vf[4];
                    ldm_x4_t(vf, vb + lm + (uint32_t)(j16 * 16 * AT_PB + dt * 32));
                    uint32_t vb0[2] = {vf[0], vf[1]};
                    uint32_t vb1[2] = {vf[2], vf[3]};
                    mma_fp(O[2*dt],   ph, vb0);
                    mma_fp(O[2*dt+1], ph, vb1);
                }
            }
        }
        __syncthreads();
    }

    // epilogue: normalize, write fp16 y[b, t, h*64+d]
    const int b = bh >> 4, h = bh & 15;
    const float inv0 = 1.0f / li[0];
    const float inv1 = 1.0f / li[1];
    const int r  = lane >> 2;
    const int cc = 2 * (lane & 3);
    const int t0 = q0 + wid * 16 + r;
    #pragma unroll
    for (int dt = 0; dt < 8; dt++) {
        const int d = h * 64 + 8 * dt + cc;
        *(uint32_t*)(g_Yh + ((size_t)b * T_ + t0) * C_ + d) =
            packf(O[dt][0] * inv0, O[dt][1] * inv0);
        *(uint32_t*)(g_Yh + ((size_t)b * T_ + t0 + 8) * C_ + d) =
            packf(O[dt][2] * inv1, O[dt][3] * inv1);
    }
}

// ---------------------------------------------------------------------------
extern "C" void kernel_launch(void* const* d_in, const int* in_sizes, int n_in,
                              void* d_out, int out_size)
{
    const float* x  = (const float*)d_in[0];
    const float* Wq = (const float*)d_in[1];
    const float* Wk = (const float*)d_in[2];
    const float* Wv = (const float*)d_in[3];
    const float* Wo = (const float*)d_in[4];
    float* out = (float*)d_out;

    __half *xh, *yh;
    cudaGetSymbolAddress((void**)&xh, g_Xh);
    cudaGetSymbolAddress((void**)&yh, g_Yh);

    cudaFuncSetAttribute(proj2<0>, cudaFuncAttributeMaxDynamicSharedMemorySize,
                         PJ_SMEM);
    cudaFuncSetAttribute(proj2<1>, cudaFuncAttributeMaxDynamicSharedMemorySize,
                         PJ_SMEM);
    cudaFuncSetAttribute(attn_mma, cudaFuncAttributeMaxDynamicSharedMemorySize,
                         AT_SMEM);

    preconv<<<dim3(1024, 5), 256>>>(x, Wq, Wk, Wv, Wo);

    // fused QKV projection (single-pass) -> fp16 scratch
    proj2<0><<<dim3(24, M_/128), 256, PJ_SMEM>>>(xh, nullptr);

    // tensor-core flash attention
    attn_mma<<<dim3(T_/128, B_*H_), 256, AT_SMEM>>>();

    // output projection (single-pass Yh)
    proj2<1><<<dim3(8, M_/128), 256, PJ_SMEM>>>(yh, out);
}